// round 3
// baseline (speedup 1.0000x reference)
#include <cuda_runtime.h>
#include <cuda_bf16.h>
#include <cstdint>

#define N_NODES 50000
#define N_EDGES 800000
#define NUM_RELS 16
#define IN_DIM 128
#define H_DIM 128
#define OUT_DIM 64

// Scratch (device globals: allocation-free rule)
__device__ float g_T1[(size_t)N_NODES * NUM_RELS * H_DIM];   // 409.6 MB
__device__ float g_H [(size_t)N_NODES * H_DIM];              // 25.6 MB
__device__ float g_T2[(size_t)N_NODES * NUM_RELS * OUT_DIM]; // 204.8 MB

// ---------------------------------------------------------------------------
// transform: T[n, r, :] = X[n, :] @ W[r]   (X: [N,128], W: [R,128,OUTD])
// TM=64 node tile per block, one relation per blockIdx.y.
// Thread microtile: RPT rows x 8 cols, K streamed in 16-chunks through smem.
// ---------------------------------------------------------------------------
template<int OUTD, int RELU>
__global__ __launch_bounds__(256)
void transform_kernel(const float* __restrict__ X,
                      const float* __restrict__ W,
                      float* __restrict__ T,
                      int nNodes)
{
    constexpr int TM = 64;
    constexpr int K  = 128;
    constexpr int KC = 16;
    constexpr int KP = K + 4;            // pad: 4-bank shift/row, keeps 16B align
    __shared__ float sX[TM][KP];         // 33.8 KB
    __shared__ float sW[KC][OUTD];       // 8 KB (128) / 4 KB (64)

    const int tid = threadIdx.x;
    const int r   = blockIdx.y;
    const int n0  = blockIdx.x * TM;
    const float* Wr = W + (size_t)r * K * OUTD;

    // Load X tile (vectorized, zero-padded at tail, optional fused ReLU)
    for (int i = tid; i < TM * (K / 4); i += 256) {
        int row = i / (K / 4);
        int c   = (i % (K / 4)) * 4;
        float4 v = make_float4(0.f, 0.f, 0.f, 0.f);
        if (n0 + row < nNodes) {
            v = *(const float4*)(X + (size_t)(n0 + row) * K + c);
            if (RELU) {
                v.x = fmaxf(v.x, 0.f); v.y = fmaxf(v.y, 0.f);
                v.z = fmaxf(v.z, 0.f); v.w = fmaxf(v.w, 0.f);
            }
        }
        *(float4*)&sX[row][c] = v;
    }

    constexpr int CO  = OUTD / 8;        // col octets: 16 (128) / 8 (64)
    constexpr int RG  = 256 / CO;        // row groups: 16 / 32
    constexpr int RPT = TM / RG;         // rows per thread: 4 / 2
    const int tx = tid % CO;
    const int ty = tid / CO;

    float acc[RPT][8];
    #pragma unroll
    for (int a = 0; a < RPT; a++)
        #pragma unroll
        for (int b = 0; b < 8; b++) acc[a][b] = 0.f;

    for (int kk = 0; kk < K; kk += KC) {
        __syncthreads();
        // Stage W chunk [KC x OUTD]
        for (int i = tid; i < KC * (OUTD / 4); i += 256) {
            int kr = i / (OUTD / 4);
            int c  = (i % (OUTD / 4)) * 4;
            *(float4*)&sW[kr][c] = *(const float4*)(Wr + (size_t)(kk + kr) * OUTD + c);
        }
        __syncthreads();

        #pragma unroll
        for (int k = 0; k < KC; k++) {
            float4 wa = *(float4*)&sW[k][tx * 8];
            float4 wb = *(float4*)&sW[k][tx * 8 + 4];
            #pragma unroll
            for (int rr = 0; rr < RPT; rr++) {
                float x = sX[ty * RPT + rr][kk + k];
                acc[rr][0] = fmaf(x, wa.x, acc[rr][0]);
                acc[rr][1] = fmaf(x, wa.y, acc[rr][1]);
                acc[rr][2] = fmaf(x, wa.z, acc[rr][2]);
                acc[rr][3] = fmaf(x, wa.w, acc[rr][3]);
                acc[rr][4] = fmaf(x, wb.x, acc[rr][4]);
                acc[rr][5] = fmaf(x, wb.y, acc[rr][5]);
                acc[rr][6] = fmaf(x, wb.z, acc[rr][6]);
                acc[rr][7] = fmaf(x, wb.w, acc[rr][7]);
            }
        }
    }

    #pragma unroll
    for (int rr = 0; rr < RPT; rr++) {
        int n = n0 + ty * RPT + rr;
        if (n < nNodes) {
            float* p = T + ((size_t)n * NUM_RELS + r) * OUTD + tx * 8;
            *(float4*)(p)     = make_float4(acc[rr][0], acc[rr][1], acc[rr][2], acc[rr][3]);
            *(float4*)(p + 4) = make_float4(acc[rr][4], acc[rr][5], acc[rr][6], acc[rr][7]);
        }
    }
}

// ---------------------------------------------------------------------------
// scatter: out[dst[e], :] += T[src[e], etype[e], :] * norm[e]
// OUTD/4 lanes per edge, vector red.global.add.v4.f32 (L2 atomic, 4x fewer ops)
// ---------------------------------------------------------------------------
template<int OUTD>
__global__ __launch_bounds__(256)
void scatter_kernel(const float* __restrict__ T,
                    const float* __restrict__ norm,
                    const int* __restrict__ src,
                    const int* __restrict__ dstv,
                    const int* __restrict__ et,
                    float* __restrict__ out,
                    int nEdges)
{
    constexpr int LPE = OUTD / 4;        // lanes per edge: 32 / 16
    const int gwarp = (blockIdx.x * 256 + threadIdx.x) >> 5;
    const int lane  = threadIdx.x & 31;
    const int e = gwarp * (32 / LPE) + lane / LPE;
    if (e >= nEdges) return;
    const int l = lane % LPE;

    int   s  = __ldg(&src[e]);
    int   d  = __ldg(&dstv[e]);
    int   t  = __ldg(&et[e]);
    float nv = __ldg(&norm[e]);

    float4 v = *(const float4*)(T + ((size_t)s * NUM_RELS + t) * OUTD + l * 4);
    v.x *= nv; v.y *= nv; v.z *= nv; v.w *= nv;

    float* p = out + (size_t)d * OUTD + l * 4;
    asm volatile("red.global.add.v4.f32 [%0], {%1, %2, %3, %4};"
                 :: "l"(p), "f"(v.x), "f"(v.y), "f"(v.z), "f"(v.w)
                 : "memory");
}

__global__ void zero_kernel(float4* __restrict__ p, int n4)
{
    int i = blockIdx.x * 256 + threadIdx.x;
    if (i < n4) p[i] = make_float4(0.f, 0.f, 0.f, 0.f);
}

extern "C" void kernel_launch(void* const* d_in, const int* in_sizes, int n_in,
                              void* d_out, int out_size)
{
    const float* feat = (const float*)d_in[0];
    const float* norm = (const float*)d_in[1];
    const float* W1   = (const float*)d_in[2];
    const float* W2   = (const float*)d_in[3];
    const int*   src  = (const int*)d_in[4];
    const int*   dst  = (const int*)d_in[5];
    const int*   et   = (const int*)d_in[6];
    float*       out  = (float*)d_out;

    float *T1, *H, *T2;
    cudaGetSymbolAddress((void**)&T1, g_T1);
    cudaGetSymbolAddress((void**)&H,  g_H);
    cudaGetSymbolAddress((void**)&T2, g_T2);

    const int nTiles = (N_NODES + 63) / 64;

    // Layer 1: T1 = feat @ W1  (per relation)
    transform_kernel<H_DIM, 0><<<dim3(nTiles, NUM_RELS), 256>>>(feat, W1, T1, N_NODES);

    // Zero hidden accumulator
    {
        int n4 = N_NODES * H_DIM / 4;
        zero_kernel<<<(n4 + 255) / 256, 256>>>((float4*)H, n4);
    }

    // Scatter layer 1: H[dst] += T1[src, et] * norm   (1 edge / warp -> 100000 blocks)
    scatter_kernel<H_DIM><<<(N_EDGES + 7) / 8, 256>>>(T1, norm, src, dst, et, H, N_EDGES);

    // Layer 2: T2 = relu(H) @ W2  (ReLU fused into X load)
    transform_kernel<OUT_DIM, 1><<<dim3(nTiles, NUM_RELS), 256>>>(H, W2, T2, N_NODES);

    // Zero output (poisoned to 0xAA by harness)
    cudaMemsetAsync(out, 0, (size_t)out_size * sizeof(float));

    // Scatter layer 2 into d_out (2 edges / warp -> 50000 blocks)
    scatter_kernel<OUT_DIM><<<(N_EDGES + 15) / 16, 256>>>(T2, norm, src, dst, et, out, N_EDGES);
}

// round 5
// speedup vs baseline: 2.3387x; 2.3387x over previous
#include <cuda_runtime.h>
#include <cuda_bf16.h>
#include <cstdint>

#define N_NODES 50000
#define N_EDGES 800000
#define NUM_RELS 16
#define IN_DIM 128
#define H_DIM 128
#define OUT_DIM 64

// ---------------------------------------------------------------------------
// Scratch (device globals: allocation-free rule)
// ---------------------------------------------------------------------------
__device__ float g_T1[(size_t)N_NODES * NUM_RELS * H_DIM];   // 409.6 MB
__device__ float g_H [(size_t)N_NODES * H_DIM];              // 25.6 MB
__device__ float g_T2[(size_t)N_NODES * NUM_RELS * OUT_DIM]; // 204.8 MB
// Pre-split W^T images: bf16 hi/lo, [R][OUTD][128] row-major (n-major, k contiguous)
__device__ __nv_bfloat16 g_W1hi[NUM_RELS * 128 * 128];
__device__ __nv_bfloat16 g_W1lo[NUM_RELS * 128 * 128];
__device__ __nv_bfloat16 g_W2hi[NUM_RELS * 64 * 128];
__device__ __nv_bfloat16 g_W2lo[NUM_RELS * 64 * 128];

// ---------------------------------------------------------------------------
// Warp-MMA helpers (baseline PTX: legal on plain sm_103 target)
// ---------------------------------------------------------------------------
__device__ __forceinline__ void ldsm_x4(uint32_t r[4], uint32_t addr) {
    asm volatile("ldmatrix.sync.aligned.m8n8.x4.shared.b16 {%0,%1,%2,%3}, [%4];"
                 : "=r"(r[0]), "=r"(r[1]), "=r"(r[2]), "=r"(r[3]) : "r"(addr));
}
__device__ __forceinline__ void mma_bf16(float c[4], const uint32_t a[4],
                                         uint32_t b0, uint32_t b1) {
    asm volatile("mma.sync.aligned.m16n8k16.row.col.f32.bf16.bf16.f32 "
                 "{%0,%1,%2,%3}, {%4,%5,%6,%7}, {%8,%9}, {%0,%1,%2,%3};"
                 : "+f"(c[0]), "+f"(c[1]), "+f"(c[2]), "+f"(c[3])
                 : "r"(a[0]), "r"(a[1]), "r"(a[2]), "r"(a[3]), "r"(b0), "r"(b1));
}

// ---------------------------------------------------------------------------
// prep: W (fp32 [R,128,OUTD]) -> W^T bf16 hi/lo as [R][n][k]
// ---------------------------------------------------------------------------
template<int OUTD>
__global__ __launch_bounds__(256)
void prep_wt_kernel(const float* __restrict__ W,
                    __nv_bfloat16* __restrict__ hi,
                    __nv_bfloat16* __restrict__ lo)
{
    int r = blockIdx.x;
    const float* Wr = W + (size_t)r * 128 * OUTD;
    __nv_bfloat16* hb = hi + (size_t)r * OUTD * 128;
    __nv_bfloat16* lb = lo + (size_t)r * OUTD * 128;
    for (int i = threadIdx.x; i < OUTD * 128; i += 256) {
        int n = i >> 7, k = i & 127;
        float x = Wr[(size_t)k * OUTD + n];
        __nv_bfloat16 h = __float2bfloat16(x);
        __nv_bfloat16 l = __float2bfloat16(x - __bfloat162float(h));
        hb[(size_t)n * 128 + k] = h;
        lb[(size_t)n * 128 + k] = l;
    }
}

// ---------------------------------------------------------------------------
// transform: T[n, r, :] = X[n, :] @ W[r]  via mma.sync bf16 split-precision.
// One 128-node tile per block; loops 8 relations (grid.y=2 covers 16).
// A panels (X hi/lo) converted once; B panels (W^T hi/lo) staged per rel.
// D = Ahi@Bhi + Ahi@Blo + Alo@Bhi, fp32 register accumulators.
// ---------------------------------------------------------------------------
template<int OUTD, int RELU>
__global__ __launch_bounds__(256)
void mma_transform_kernel(const float* __restrict__ X,
                          const __nv_bfloat16* __restrict__ WThi,
                          const __nv_bfloat16* __restrict__ WTlo,
                          float* __restrict__ T)
{
    constexpr int LDA = 136;                 // 128 + 8 pad (272B row: ldmatrix conflict-free)
    constexpr int LDB = 136;
    constexpr int A_PANEL = 128 * LDA;       // elements
    constexpr int B_PANEL = OUTD * LDB;

    extern __shared__ __nv_bfloat16 sm[];
    __nv_bfloat16* sAhi = sm;
    __nv_bfloat16* sAlo = sm + A_PANEL;
    __nv_bfloat16* sBhi = sm + 2 * A_PANEL;
    __nv_bfloat16* sBlo = sm + 2 * A_PANEL + B_PANEL;

    constexpr int WARPS_N = (OUTD == 128) ? 4 : 2;
    constexpr int WARPS_M = 8 / WARPS_N;     // 2 or 4
    constexpr int WM = 128 / WARPS_M;        // 64 or 32
    constexpr int WN = OUTD / WARPS_N;       // 32
    constexpr int MFR = WM / 16;             // 4 or 2
    constexpr int NFR = WN / 8;              // 4

    const int tid = threadIdx.x, wid = tid >> 5, lane = tid & 31;
    const int wm0 = (wid / WARPS_N) * WM;
    const int wn0 = (wid % WARPS_N) * WN;
    const int n0 = blockIdx.x * 128;
    const int relBase = blockIdx.y * 8;

    // --- Convert X tile -> bf16 hi/lo A panels (zero-pad OOB rows, fused ReLU)
    for (int i = tid; i < 128 * 64; i += 256) {
        int row = i >> 6, k = (i & 63) * 2;
        float2 v = make_float2(0.f, 0.f);
        int n = n0 + row;
        if (n < N_NODES) v = *(const float2*)(X + (size_t)n * 128 + k);
        if (RELU) { v.x = fmaxf(v.x, 0.f); v.y = fmaxf(v.y, 0.f); }
        __nv_bfloat16 h0 = __float2bfloat16(v.x), h1 = __float2bfloat16(v.y);
        __nv_bfloat16 l0 = __float2bfloat16(v.x - __bfloat162float(h0));
        __nv_bfloat16 l1 = __float2bfloat16(v.y - __bfloat162float(h1));
        int o = row * LDA + k;
        __nv_bfloat162 hh; hh.x = h0; hh.y = h1;
        __nv_bfloat162 ll; ll.x = l0; ll.y = l1;
        *(__nv_bfloat162*)(sAhi + o) = hh;
        *(__nv_bfloat162*)(sAlo + o) = ll;
    }

    // Per-lane ldmatrix addressing components
    const int lr = lane & 15;                // matrix row supplied by this lane
    const int lh = lane >> 4;                // 8-col half
    const uint32_t aHiBase = (uint32_t)__cvta_generic_to_shared(sAhi);
    const uint32_t aLoBase = (uint32_t)__cvta_generic_to_shared(sAlo);
    const uint32_t bHiBase = (uint32_t)__cvta_generic_to_shared(sBhi);
    const uint32_t bLoBase = (uint32_t)__cvta_generic_to_shared(sBlo);

    for (int ri = 0; ri < 8; ri++) {
        const int r = relBase + ri;
        __syncthreads();                     // A ready (ri=0) / prior mma reads done
        {   // Stage B panels: [OUTD][128] bf16 rows (256B) -> padded smem (272B rows)
            const float4* shi = (const float4*)(WThi + (size_t)r * OUTD * 128);
            const float4* slo = (const float4*)(WTlo + (size_t)r * OUTD * 128);
            float4* dhi = (float4*)sBhi;
            float4* dlo = (float4*)sBlo;
            for (int i = tid; i < OUTD * 16; i += 256) {
                int row = i >> 4, c = i & 15;
                dhi[row * 17 + c] = shi[i];  // 17 float4 = 272B padded row
                dlo[row * 17 + c] = slo[i];
            }
        }
        __syncthreads();

        float acc[MFR][NFR][4];
        #pragma unroll
        for (int mi = 0; mi < MFR; mi++)
            #pragma unroll
            for (int ni = 0; ni < NFR; ni++)
                #pragma unroll
                for (int q = 0; q < 4; q++) acc[mi][ni][q] = 0.f;

        #pragma unroll
        for (int pass = 0; pass < 3; pass++) {
            const uint32_t aB = (pass == 2) ? aLoBase : aHiBase;
            const uint32_t bB = (pass == 1) ? bLoBase : bHiBase;
            #pragma unroll
            for (int k = 0; k < 8; k++) {
                uint32_t a[MFR][4];
                #pragma unroll
                for (int mi = 0; mi < MFR; mi++) {
                    uint32_t ad = aB + (uint32_t)(((wm0 + mi * 16 + lr) * LDA
                                                   + k * 16 + lh * 8) << 1);
                    ldsm_x4(a[mi], ad);
                }
                uint32_t b[NFR / 2][4];
                #pragma unroll
                for (int nj = 0; nj < NFR / 2; nj++) {
                    uint32_t bd = bB + (uint32_t)(((wn0 + nj * 16 + lr) * LDB
                                                   + k * 16 + lh * 8) << 1);
                    ldsm_x4(b[nj], bd);
                }
                #pragma unroll
                for (int mi = 0; mi < MFR; mi++)
                    #pragma unroll
                    for (int ni = 0; ni < NFR; ni++)
                        mma_bf16(acc[mi][ni], a[mi],
                                 b[ni >> 1][ni & 1], b[ni >> 1][2 + (ni & 1)]);
            }
        }

        // Epilogue: registers -> T[n, r, :]
        #pragma unroll
        for (int mi = 0; mi < MFR; mi++) {
            #pragma unroll
            for (int ni = 0; ni < NFR; ni++) {
                int row = wm0 + mi * 16 + (lane >> 2);
                int col = wn0 + ni * 8 + (lane & 3) * 2;
                int n1 = n0 + row;
                if (n1 < N_NODES) {
                    float* p = T + ((size_t)n1 * NUM_RELS + r) * OUTD + col;
                    *(float2*)p = make_float2(acc[mi][ni][0], acc[mi][ni][1]);
                }
                int n2 = n1 + 8;
                if (n2 < N_NODES) {
                    float* p = T + ((size_t)n2 * NUM_RELS + r) * OUTD + col;
                    *(float2*)p = make_float2(acc[mi][ni][2], acc[mi][ni][3]);
                }
            }
        }
    }
}

// ---------------------------------------------------------------------------
// scatter: out[dst[e], :] += T[src[e], etype[e], :] * norm[e]
// OUTD/4 lanes per edge, vector red.global.add.v4.f32 (L2 atomics)
// ---------------------------------------------------------------------------
template<int OUTD>
__global__ __launch_bounds__(256)
void scatter_kernel(const float* __restrict__ T,
                    const float* __restrict__ norm,
                    const int* __restrict__ src,
                    const int* __restrict__ dstv,
                    const int* __restrict__ et,
                    float* __restrict__ out,
                    int nEdges)
{
    constexpr int LPE = OUTD / 4;
    const int gwarp = (blockIdx.x * 256 + threadIdx.x) >> 5;
    const int lane  = threadIdx.x & 31;
    const int e = gwarp * (32 / LPE) + lane / LPE;
    if (e >= nEdges) return;
    const int l = lane % LPE;

    int   s  = __ldg(&src[e]);
    int   d  = __ldg(&dstv[e]);
    int   t  = __ldg(&et[e]);
    float nv = __ldg(&norm[e]);

    float4 v = *(const float4*)(T + ((size_t)s * NUM_RELS + t) * OUTD + l * 4);
    v.x *= nv; v.y *= nv; v.z *= nv; v.w *= nv;

    float* p = out + (size_t)d * OUTD + l * 4;
    asm volatile("red.global.add.v4.f32 [%0], {%1, %2, %3, %4};"
                 :: "l"(p), "f"(v.x), "f"(v.y), "f"(v.z), "f"(v.w)
                 : "memory");
}

__global__ void zero_kernel(float4* __restrict__ p, int n4)
{
    int i = blockIdx.x * 256 + threadIdx.x;
    if (i < n4) p[i] = make_float4(0.f, 0.f, 0.f, 0.f);
}

extern "C" void kernel_launch(void* const* d_in, const int* in_sizes, int n_in,
                              void* d_out, int out_size)
{
    const float* feat = (const float*)d_in[0];
    const float* norm = (const float*)d_in[1];
    const float* W1   = (const float*)d_in[2];
    const float* W2   = (const float*)d_in[3];
    const int*   src  = (const int*)d_in[4];
    const int*   dst  = (const int*)d_in[5];
    const int*   et   = (const int*)d_in[6];
    float*       out  = (float*)d_out;

    float *T1, *H, *T2;
    __nv_bfloat16 *W1h, *W1l, *W2h, *W2l;
    cudaGetSymbolAddress((void**)&T1,  g_T1);
    cudaGetSymbolAddress((void**)&H,   g_H);
    cudaGetSymbolAddress((void**)&T2,  g_T2);
    cudaGetSymbolAddress((void**)&W1h, g_W1hi);
    cudaGetSymbolAddress((void**)&W1l, g_W1lo);
    cudaGetSymbolAddress((void**)&W2h, g_W2hi);
    cudaGetSymbolAddress((void**)&W2l, g_W2lo);

    constexpr int SMEM1 = (2 * 128 * 136 + 2 * 128 * 136) * 2;  // 139264
    constexpr int SMEM2 = (2 * 128 * 136 + 2 * 64 * 136) * 2;   // 104448
    cudaFuncSetAttribute(mma_transform_kernel<H_DIM, 0>,
                         cudaFuncAttributeMaxDynamicSharedMemorySize, SMEM1);
    cudaFuncSetAttribute(mma_transform_kernel<OUT_DIM, 1>,
                         cudaFuncAttributeMaxDynamicSharedMemorySize, SMEM2);

    const int nTiles = (N_NODES + 127) / 128;  // 391

    // Pre-split / pre-transpose weights (tiny; L2-hot afterwards)
    prep_wt_kernel<H_DIM><<<NUM_RELS, 256>>>(W1, W1h, W1l);
    prep_wt_kernel<OUT_DIM><<<NUM_RELS, 256>>>(W2, W2h, W2l);

    // Layer 1 transform: T1 = feat @ W1 (HMMA, split bf16)
    mma_transform_kernel<H_DIM, 0><<<dim3(nTiles, 2), 256, SMEM1>>>(feat, W1h, W1l, T1);

    // Zero hidden accumulator
    {
        int n4 = N_NODES * H_DIM / 4;
        zero_kernel<<<(n4 + 255) / 256, 256>>>((float4*)H, n4);
    }

    // Scatter layer 1: H[dst] += T1[src, et] * norm
    scatter_kernel<H_DIM><<<(N_EDGES + 7) / 8, 256>>>(T1, norm, src, dst, et, H, N_EDGES);

    // Layer 2 transform: T2 = relu(H) @ W2 (ReLU fused into conversion)
    mma_transform_kernel<OUT_DIM, 1><<<dim3(nTiles, 2), 256, SMEM2>>>(H, W2h, W2l, T2);

    // Zero output (harness poisons to 0xAA)
    cudaMemsetAsync(out, 0, (size_t)out_size * sizeof(float));

    // Scatter layer 2 into d_out
    scatter_kernel<OUT_DIM><<<(N_EDGES + 15) / 16, 256>>>(T2, norm, src, dst, et, out, N_EDGES);
}

// round 7
// speedup vs baseline: 2.9188x; 1.2481x over previous
#include <cuda_runtime.h>
#include <cuda_bf16.h>
#include <cstdint>

#define N_NODES 50000
#define N_EDGES 800000
#define NUM_RELS 16
#define IN_DIM 128
#define H_DIM 128
#define OUT_DIM 64

#define N_TILES 391                 // ceil(50000/128)
#define NBINS (N_TILES * NUM_RELS)  // 6256

// ---------------------------------------------------------------------------
// Scratch (device globals: allocation-free rule)
// ---------------------------------------------------------------------------
__device__ float g_H[(size_t)N_NODES * H_DIM];               // 25.6 MB
// Edge binning: key = (src>>7)*16 + etype
__device__ int    g_binCnt[NBINS];
__device__ int    g_binOff[NBINS];
__device__ int    g_binCur[NBINS];
__device__ float4 g_pack[N_EDGES];  // {row_in_tile, dst, norm, -} per edge, bin-ordered
// Pre-split W^T images: bf16 hi/lo, [R][OUTD][128] row-major (n-major, k contiguous)
__device__ __nv_bfloat16 g_W1hi[NUM_RELS * 128 * 128];
__device__ __nv_bfloat16 g_W1lo[NUM_RELS * 128 * 128];
__device__ __nv_bfloat16 g_W2hi[NUM_RELS * 64 * 128];
__device__ __nv_bfloat16 g_W2lo[NUM_RELS * 64 * 128];

// ---------------------------------------------------------------------------
// Warp-MMA helpers (baseline PTX: legal on plain sm_103 target)
// ---------------------------------------------------------------------------
__device__ __forceinline__ void ldsm_x4(uint32_t r[4], uint32_t addr) {
    asm volatile("ldmatrix.sync.aligned.m8n8.x4.shared.b16 {%0,%1,%2,%3}, [%4];"
                 : "=r"(r[0]), "=r"(r[1]), "=r"(r[2]), "=r"(r[3]) : "r"(addr));
}
__device__ __forceinline__ void mma_bf16(float c[4], const uint32_t a[4],
                                         uint32_t b0, uint32_t b1) {
    asm volatile("mma.sync.aligned.m16n8k16.row.col.f32.bf16.bf16.f32 "
                 "{%0,%1,%2,%3}, {%4,%5,%6,%7}, {%8,%9}, {%0,%1,%2,%3};"
                 : "+f"(c[0]), "+f"(c[1]), "+f"(c[2]), "+f"(c[3])
                 : "r"(a[0]), "r"(a[1]), "r"(a[2]), "r"(a[3]), "r"(b0), "r"(b1));
}

// ---------------------------------------------------------------------------
// Edge binning kernels
// ---------------------------------------------------------------------------
__global__ void bin_reset_kernel(int* __restrict__ cnt, int* __restrict__ cur)
{
    int i = blockIdx.x * 256 + threadIdx.x;
    if (i < NBINS) { cnt[i] = 0; cur[i] = 0; }
}

__global__ void bin_count_kernel(const int* __restrict__ src,
                                 const int* __restrict__ et,
                                 int* __restrict__ cnt)
{
    int e = blockIdx.x * 256 + threadIdx.x;
    if (e < N_EDGES)
        atomicAdd(&cnt[(src[e] >> 7) * NUM_RELS + et[e]], 1);
}

__global__ __launch_bounds__(256)
void bin_scan_kernel(const int* __restrict__ cnt, int* __restrict__ off)
{
    __shared__ int s[256];
    const int tid = threadIdx.x;
    constexpr int PER = (NBINS + 255) / 256;  // 25
    int loc[PER];
    int base = tid * PER, sum = 0;
    #pragma unroll
    for (int i = 0; i < PER; i++) {
        int idx = base + i;
        int v = (idx < NBINS) ? cnt[idx] : 0;
        loc[i] = v; sum += v;
    }
    s[tid] = sum;
    __syncthreads();
    for (int d = 1; d < 256; d <<= 1) {
        int v = (tid >= d) ? s[tid - d] : 0;
        __syncthreads();
        s[tid] += v;
        __syncthreads();
    }
    int run = tid ? s[tid - 1] : 0;
    #pragma unroll
    for (int i = 0; i < PER; i++) {
        int idx = base + i;
        if (idx < NBINS) { off[idx] = run; run += loc[i]; }
    }
}

__global__ void bin_fill_kernel(const int* __restrict__ src,
                                const int* __restrict__ dstv,
                                const int* __restrict__ et,
                                const float* __restrict__ norm,
                                const int* __restrict__ off,
                                int* __restrict__ cur,
                                float4* __restrict__ pack)
{
    int e = blockIdx.x * 256 + threadIdx.x;
    if (e >= N_EDGES) return;
    int s = src[e];
    int bin = (s >> 7) * NUM_RELS + et[e];
    int pos = off[bin] + atomicAdd(&cur[bin], 1);
    float4 p;
    p.x = __int_as_float(s & 127);
    p.y = __int_as_float(dstv[e]);
    p.z = norm[e];
    p.w = 0.f;
    pack[pos] = p;
}

// ---------------------------------------------------------------------------
// prep: W (fp32 [R,128,OUTD]) -> W^T bf16 hi/lo as [R][n][k]
// ---------------------------------------------------------------------------
template<int OUTD>
__global__ __launch_bounds__(256)
void prep_wt_kernel(const float* __restrict__ W,
                    __nv_bfloat16* __restrict__ hi,
                    __nv_bfloat16* __restrict__ lo)
{
    int r = blockIdx.x;
    const float* Wr = W + (size_t)r * 128 * OUTD;
    __nv_bfloat16* hb = hi + (size_t)r * OUTD * 128;
    __nv_bfloat16* lb = lo + (size_t)r * OUTD * 128;
    for (int i = threadIdx.x; i < OUTD * 128; i += 256) {
        int n = i >> 7, k = i & 127;
        float x = Wr[(size_t)k * OUTD + n];
        __nv_bfloat16 h = __float2bfloat16(x);
        __nv_bfloat16 l = __float2bfloat16(x - __bfloat162float(h));
        hb[(size_t)n * 128 + k] = h;
        lb[(size_t)n * 128 + k] = l;
    }
}

// ---------------------------------------------------------------------------
// Fused transform+scatter: for each (128-node tile, rel):
//   tile = X[tile] @ W[rel]      (HMMA split-bf16, fp32 acc)
//   for edges in bin(tile, rel): accOut[dst] += tile[src&127] * norm  (L2 red)
// One node tile per block, loops 8 relations (grid.y=2 covers 16).
// The fp32 tile reuses the (dead) B-panel smem between MMA and next staging.
// ---------------------------------------------------------------------------
template<int OUTD, int RELU>
__global__ __launch_bounds__(256)
void fused_transform_kernel(const float* __restrict__ X,
                            const __nv_bfloat16* __restrict__ WThi,
                            const __nv_bfloat16* __restrict__ WTlo,
                            float* __restrict__ accOut,
                            const float4* __restrict__ pack,
                            const int* __restrict__ binOff,
                            const int* __restrict__ binCnt)
{
    constexpr int LDA = 136;                 // bf16 elems; 272B row (ldmatrix-friendly)
    constexpr int LDB = 136;
    constexpr int A_PANEL = 128 * LDA;
    constexpr int B_PANEL = OUTD * LDB;
    constexpr int LDT = OUTD + 4;            // fp32 tile stride (16B-aligned rows)

    extern __shared__ __nv_bfloat16 sm[];
    __nv_bfloat16* sAhi = sm;
    __nv_bfloat16* sAlo = sm + A_PANEL;
    __nv_bfloat16* sBhi = sm + 2 * A_PANEL;  // union region start
    __nv_bfloat16* sBlo = sBhi + B_PANEL;
    float* sTile = (float*)sBhi;             // overlays B panels after MMA

    constexpr int WARPS_N = (OUTD == 128) ? 4 : 2;
    constexpr int WARPS_M = 8 / WARPS_N;     // 2 or 4
    constexpr int WM = 128 / WARPS_M;        // 64 or 32
    constexpr int WN = OUTD / WARPS_N;       // 32
    constexpr int MFR = WM / 16;             // 4 or 2
    constexpr int NFR = WN / 8;              // 4

    const int tid = threadIdx.x, wid = tid >> 5, lane = tid & 31;
    const int wm0 = (wid / WARPS_N) * WM;
    const int wn0 = (wid % WARPS_N) * WN;
    const int n0 = blockIdx.x * 128;
    const int relBase = blockIdx.y * 8;

    // --- Convert X tile -> bf16 hi/lo A panels (zero-pad OOB rows, fused ReLU)
    for (int i = tid; i < 128 * 64; i += 256) {
        int row = i >> 6, k = (i & 63) * 2;
        float2 v = make_float2(0.f, 0.f);
        int n = n0 + row;
        if (n < N_NODES) v = *(const float2*)(X + (size_t)n * 128 + k);
        if (RELU) { v.x = fmaxf(v.x, 0.f); v.y = fmaxf(v.y, 0.f); }
        __nv_bfloat16 h0 = __float2bfloat16(v.x), h1 = __float2bfloat16(v.y);
        __nv_bfloat16 l0 = __float2bfloat16(v.x - __bfloat162float(h0));
        __nv_bfloat16 l1 = __float2bfloat16(v.y - __bfloat162float(h1));
        int o = row * LDA + k;
        __nv_bfloat162 hh; hh.x = h0; hh.y = h1;
        __nv_bfloat162 ll; ll.x = l0; ll.y = l1;
        *(__nv_bfloat162*)(sAhi + o) = hh;
        *(__nv_bfloat162*)(sAlo + o) = ll;
    }

    const int lr = lane & 15;
    const int lh = lane >> 4;
    const uint32_t aHiBase = (uint32_t)__cvta_generic_to_shared(sAhi);
    const uint32_t aLoBase = (uint32_t)__cvta_generic_to_shared(sAlo);
    const uint32_t bHiBase = (uint32_t)__cvta_generic_to_shared(sBhi);
    const uint32_t bLoBase = (uint32_t)__cvta_generic_to_shared(sBlo);

    for (int ri = 0; ri < 8; ri++) {
        const int r = relBase + ri;
        __syncthreads();   // A ready (ri=0) / previous scatter done with sTile
        {   // Stage B panels: [OUTD][128] bf16 rows -> padded smem (272B rows)
            const float4* shi = (const float4*)(WThi + (size_t)r * OUTD * 128);
            const float4* slo = (const float4*)(WTlo + (size_t)r * OUTD * 128);
            float4* dhi = (float4*)sBhi;
            float4* dlo = (float4*)sBlo;
            for (int i = tid; i < OUTD * 16; i += 256) {
                int row = i >> 4, c = i & 15;
                dhi[row * 17 + c] = shi[i];
                dlo[row * 17 + c] = slo[i];
            }
        }
        __syncthreads();

        float acc[MFR][NFR][4];
        #pragma unroll
        for (int mi = 0; mi < MFR; mi++)
            #pragma unroll
            for (int ni = 0; ni < NFR; ni++)
                #pragma unroll
                for (int q = 0; q < 4; q++) acc[mi][ni][q] = 0.f;

        // Single k-loop; all 3 split products accumulate into the same acc.
        #pragma unroll
        for (int k = 0; k < 8; k++) {
            const uint32_t kofs = (uint32_t)((k * 16 + lh * 8) << 1);
            uint32_t ah[MFR][4], al[MFR][4], bh[NFR / 2][4], bl[NFR / 2][4];
            #pragma unroll
            for (int mi = 0; mi < MFR; mi++) {
                uint32_t rofs = (uint32_t)(((wm0 + mi * 16 + lr) * LDA) << 1) + kofs;
                ldsm_x4(ah[mi], aHiBase + rofs);
                ldsm_x4(al[mi], aLoBase + rofs);
            }
            #pragma unroll
            for (int nj = 0; nj < NFR / 2; nj++) {
                uint32_t rofs = (uint32_t)(((wn0 + nj * 16 + lr) * LDB) << 1) + kofs;
                ldsm_x4(bh[nj], bHiBase + rofs);
                ldsm_x4(bl[nj], bLoBase + rofs);
            }
            #pragma unroll
            for (int mi = 0; mi < MFR; mi++)
                #pragma unroll
                for (int ni = 0; ni < NFR; ni++) {
                    mma_bf16(acc[mi][ni], ah[mi], bh[ni >> 1][ni & 1], bh[ni >> 1][2 + (ni & 1)]);
                    mma_bf16(acc[mi][ni], ah[mi], bl[ni >> 1][ni & 1], bl[ni >> 1][2 + (ni & 1)]);
                    mma_bf16(acc[mi][ni], al[mi], bh[ni >> 1][ni & 1], bh[ni >> 1][2 + (ni & 1)]);
                }
        }

        __syncthreads();   // all warps done reading B panels -> safe to overlay tile

        // Epilogue: acc -> fp32 smem tile
        #pragma unroll
        for (int mi = 0; mi < MFR; mi++)
            #pragma unroll
            for (int ni = 0; ni < NFR; ni++) {
                int row = wm0 + mi * 16 + (lane >> 2);
                int col = wn0 + ni * 8 + (lane & 3) * 2;
                *(float2*)&sTile[row * LDT + col] =
                    make_float2(acc[mi][ni][0], acc[mi][ni][1]);
                *(float2*)&sTile[(row + 8) * LDT + col] =
                    make_float2(acc[mi][ni][2], acc[mi][ni][3]);
            }
        __syncthreads();   // tile visible

        // Scatter this bin's edges: accOut[dst] += tile[row] * norm
        {
            const int bin = blockIdx.x * NUM_RELS + r;
            const int off = binOff[bin];
            const int cnt = binCnt[bin];
            if (OUTD == 128) {
                for (int j = wid; j < cnt; j += 8) {
                    float4 pk = pack[off + j];            // broadcast load
                    int row = __float_as_int(pk.x);
                    int d   = __float_as_int(pk.y);
                    float nv = pk.z;
                    float4 v = *(const float4*)&sTile[row * LDT + lane * 4];
                    v.x *= nv; v.y *= nv; v.z *= nv; v.w *= nv;
                    float* p = accOut + (size_t)d * OUTD + lane * 4;
                    asm volatile("red.global.add.v4.f32 [%0], {%1, %2, %3, %4};"
                                 :: "l"(p), "f"(v.x), "f"(v.y), "f"(v.z), "f"(v.w)
                                 : "memory");
                }
            } else {       // OUTD == 64: 2 edges per warp
                const int sub = lane >> 4, l = lane & 15;
                for (int j = wid * 2; j < cnt; j += 16) {
                    int jj = j + sub;
                    if (jj < cnt) {
                        float4 pk = pack[off + jj];
                        int row = __float_as_int(pk.x);
                        int d   = __float_as_int(pk.y);
                        float nv = pk.z;
                        float4 v = *(const float4*)&sTile[row * LDT + l * 4];
                        v.x *= nv; v.y *= nv; v.z *= nv; v.w *= nv;
                        float* p = accOut + (size_t)d * OUTD + l * 4;
                        asm volatile("red.global.add.v4.f32 [%0], {%1, %2, %3, %4};"
                                     :: "l"(p), "f"(v.x), "f"(v.y), "f"(v.z), "f"(v.w)
                                     : "memory");
                    }
                }
            }
        }
    }
}

__global__ void zero_kernel(float4* __restrict__ p, int n4)
{
    int i = blockIdx.x * 256 + threadIdx.x;
    if (i < n4) p[i] = make_float4(0.f, 0.f, 0.f, 0.f);
}

extern "C" void kernel_launch(void* const* d_in, const int* in_sizes, int n_in,
                              void* d_out, int out_size)
{
    const float* feat = (const float*)d_in[0];
    const float* norm = (const float*)d_in[1];
    const float* W1   = (const float*)d_in[2];
    const float* W2   = (const float*)d_in[3];
    const int*   src  = (const int*)d_in[4];
    const int*   dst  = (const int*)d_in[5];
    const int*   et   = (const int*)d_in[6];
    float*       out  = (float*)d_out;

    float *H;
    int *binCnt, *binOff, *binCur;
    float4 *pack;
    __nv_bfloat16 *W1h, *W1l, *W2h, *W2l;
    cudaGetSymbolAddress((void**)&H,      g_H);
    cudaGetSymbolAddress((void**)&binCnt, g_binCnt);
    cudaGetSymbolAddress((void**)&binOff, g_binOff);
    cudaGetSymbolAddress((void**)&binCur, g_binCur);
    cudaGetSymbolAddress((void**)&pack,   g_pack);
    cudaGetSymbolAddress((void**)&W1h,    g_W1hi);
    cudaGetSymbolAddress((void**)&W1l,    g_W1lo);
    cudaGetSymbolAddress((void**)&W2h,    g_W2hi);
    cudaGetSymbolAddress((void**)&W2l,    g_W2lo);

    // smem: A panels + max(B panels, fp32 tile)
    constexpr int SMEM1 = 2 * (128 * 136 * 2)
                        + ((2 * 128 * 136 * 2 > 128 * 132 * 4) ? 2 * 128 * 136 * 2
                                                               : 128 * 132 * 4);
    constexpr int SMEM2 = 2 * (128 * 136 * 2)
                        + ((2 * 64 * 136 * 2 > 128 * 68 * 4) ? 2 * 64 * 136 * 2
                                                             : 128 * 68 * 4);
    cudaFuncSetAttribute(fused_transform_kernel<H_DIM, 0>,
                         cudaFuncAttributeMaxDynamicSharedMemorySize, SMEM1);
    cudaFuncSetAttribute(fused_transform_kernel<OUT_DIM, 1>,
                         cudaFuncAttributeMaxDynamicSharedMemorySize, SMEM2);

    // --- Edge binning by (src tile, etype): shared by both layers
    bin_reset_kernel<<<(NBINS + 255) / 256, 256>>>(binCnt, binCur);
    bin_count_kernel<<<(N_EDGES + 255) / 256, 256>>>(src, et, binCnt);
    bin_scan_kernel<<<1, 256>>>(binCnt, binOff);
    bin_fill_kernel<<<(N_EDGES + 255) / 256, 256>>>(src, dst, et, norm,
                                                    binOff, binCur, pack);

    // --- Weight pre-split / pre-transpose (tiny; L2-hot afterwards)
    prep_wt_kernel<H_DIM><<<NUM_RELS, 256>>>(W1, W1h, W1l);
    prep_wt_kernel<OUT_DIM><<<NUM_RELS, 256>>>(W2, W2h, W2l);

    // --- Layer 1: H[dst] += (feat @ W1[r])[src] * norm, fused
    {
        int n4 = N_NODES * H_DIM / 4;
        zero_kernel<<<(n4 + 255) / 256, 256>>>((float4*)H, n4);
    }
    fused_transform_kernel<H_DIM, 0><<<dim3(N_TILES, 2), 256, SMEM1>>>(
        feat, W1h, W1l, H, pack, binOff, binCnt);

    // --- Layer 2: out[dst] += (relu(H) @ W2[r])[src] * norm, fused
    cudaMemsetAsync(out, 0, (size_t)out_size * sizeof(float));
    fused_transform_kernel<OUT_DIM, 1><<<dim3(N_TILES, 2), 256, SMEM2>>>(
        H, W2h, W2l, out, pack, binOff, binCnt);
}

// round 8
// speedup vs baseline: 3.0766x; 1.0540x over previous
#include <cuda_runtime.h>
#include <cuda_bf16.h>
#include <cstdint>

#define N_NODES 50000
#define N_EDGES 800000
#define NUM_RELS 16
#define IN_DIM 128
#define H_DIM 128
#define OUT_DIM 64

#define N_TILES 391                 // ceil(50000/128)
#define NBINS (N_TILES * NUM_RELS)  // 6256

// ---------------------------------------------------------------------------
// Scratch (device globals: allocation-free rule)
// ---------------------------------------------------------------------------
__device__ float g_H[(size_t)N_NODES * H_DIM];               // 25.6 MB
__device__ int    g_binCnt[NBINS];
__device__ int    g_binOff[NBINS];
__device__ int    g_binCur[NBINS];
__device__ float4 g_pack[N_EDGES];  // {row_in_tile, dst, norm, -} bin-ordered
__device__ __nv_bfloat16 g_W1hi[NUM_RELS * 128 * 128];
__device__ __nv_bfloat16 g_W1lo[NUM_RELS * 128 * 128];
__device__ __nv_bfloat16 g_W2hi[NUM_RELS * 64 * 128];
__device__ __nv_bfloat16 g_W2lo[NUM_RELS * 64 * 128];

// ---------------------------------------------------------------------------
// Warp-MMA helpers (baseline PTX: legal on plain sm_103 target)
// ---------------------------------------------------------------------------
__device__ __forceinline__ void ldsm_x4(uint32_t r[4], uint32_t addr) {
    asm volatile("ldmatrix.sync.aligned.m8n8.x4.shared.b16 {%0,%1,%2,%3}, [%4];"
                 : "=r"(r[0]), "=r"(r[1]), "=r"(r[2]), "=r"(r[3]) : "r"(addr));
}
__device__ __forceinline__ void mma_bf16(float c[4], const uint32_t a[4],
                                         uint32_t b0, uint32_t b1) {
    asm volatile("mma.sync.aligned.m16n8k16.row.col.f32.bf16.bf16.f32 "
                 "{%0,%1,%2,%3}, {%4,%5,%6,%7}, {%8,%9}, {%0,%1,%2,%3};"
                 : "+f"(c[0]), "+f"(c[1]), "+f"(c[2]), "+f"(c[3])
                 : "r"(a[0]), "r"(a[1]), "r"(a[2]), "r"(a[3]), "r"(b0), "r"(b1));
}

// ---------------------------------------------------------------------------
// Edge binning kernels
// ---------------------------------------------------------------------------
__global__ void bin_reset_kernel(int* __restrict__ cnt, int* __restrict__ cur)
{
    int i = blockIdx.x * 256 + threadIdx.x;
    if (i < NBINS) { cnt[i] = 0; cur[i] = 0; }
}

__global__ void bin_count_kernel(const int* __restrict__ src,
                                 const int* __restrict__ et,
                                 int* __restrict__ cnt)
{
    int e = blockIdx.x * 256 + threadIdx.x;
    if (e < N_EDGES)
        atomicAdd(&cnt[(src[e] >> 7) * NUM_RELS + et[e]], 1);
}

__global__ __launch_bounds__(256)
void bin_scan_kernel(const int* __restrict__ cnt, int* __restrict__ off)
{
    __shared__ int s[256];
    const int tid = threadIdx.x;
    constexpr int PER = (NBINS + 255) / 256;  // 25
    int loc[PER];
    int base = tid * PER, sum = 0;
    #pragma unroll
    for (int i = 0; i < PER; i++) {
        int idx = base + i;
        int v = (idx < NBINS) ? cnt[idx] : 0;
        loc[i] = v; sum += v;
    }
    s[tid] = sum;
    __syncthreads();
    for (int d = 1; d < 256; d <<= 1) {
        int v = (tid >= d) ? s[tid - d] : 0;
        __syncthreads();
        s[tid] += v;
        __syncthreads();
    }
    int run = tid ? s[tid - 1] : 0;
    #pragma unroll
    for (int i = 0; i < PER; i++) {
        int idx = base + i;
        if (idx < NBINS) { off[idx] = run; run += loc[i]; }
    }
}

__global__ void bin_fill_kernel(const int* __restrict__ src,
                                const int* __restrict__ dstv,
                                const int* __restrict__ et,
                                const float* __restrict__ norm,
                                const int* __restrict__ off,
                                int* __restrict__ cur,
                                float4* __restrict__ pack)
{
    int e = blockIdx.x * 256 + threadIdx.x;
    if (e >= N_EDGES) return;
    int s = src[e];
    int bin = (s >> 7) * NUM_RELS + et[e];
    int pos = off[bin] + atomicAdd(&cur[bin], 1);
    float4 p;
    p.x = __int_as_float(s & 127);
    p.y = __int_as_float(dstv[e]);
    p.z = norm[e];
    p.w = 0.f;
    pack[pos] = p;
}

// ---------------------------------------------------------------------------
// prep: W (fp32 [R,128,OUTD]) -> W^T bf16 hi/lo as [R][n][k]
// ---------------------------------------------------------------------------
template<int OUTD>
__global__ __launch_bounds__(256)
void prep_wt_kernel(const float* __restrict__ W,
                    __nv_bfloat16* __restrict__ hi,
                    __nv_bfloat16* __restrict__ lo)
{
    int r = blockIdx.x;
    const float* Wr = W + (size_t)r * 128 * OUTD;
    __nv_bfloat16* hb = hi + (size_t)r * OUTD * 128;
    __nv_bfloat16* lb = lo + (size_t)r * OUTD * 128;
    for (int i = threadIdx.x; i < OUTD * 128; i += 256) {
        int n = i >> 7, k = i & 127;
        float x = Wr[(size_t)k * OUTD + n];
        __nv_bfloat16 h = __float2bfloat16(x);
        __nv_bfloat16 l = __float2bfloat16(x - __bfloat162float(h));
        hb[(size_t)n * 128 + k] = h;
        lb[(size_t)n * 128 + k] = l;
    }
}

// ---------------------------------------------------------------------------
// Fused transform+scatter, 512 threads (16 warps, 4x4 warp grid).
// For each (128-node tile, rel):
//   tile = X[tile] @ W[rel]      (HMMA split-bf16, fp32 acc)
//   for edges in bin(tile, rel): accOut[dst] += tile[src&127] * norm  (L2 red)
// ---------------------------------------------------------------------------
template<int OUTD, int RELU>
__global__ __launch_bounds__(512, 1)
void fused_transform_kernel(const float* __restrict__ X,
                            const __nv_bfloat16* __restrict__ WThi,
                            const __nv_bfloat16* __restrict__ WTlo,
                            float* __restrict__ accOut,
                            const float4* __restrict__ pack,
                            const int* __restrict__ binOff,
                            const int* __restrict__ binCnt)
{
    constexpr int LDA = 136;                 // bf16 elems; 272B row (ldmatrix-friendly)
    constexpr int LDB = 136;
    constexpr int A_PANEL = 128 * LDA;
    constexpr int B_PANEL = OUTD * LDB;
    constexpr int LDT = OUTD + 4;            // fp32 tile stride

    extern __shared__ __nv_bfloat16 sm[];
    __nv_bfloat16* sAhi = sm;
    __nv_bfloat16* sAlo = sm + A_PANEL;
    __nv_bfloat16* sBhi = sm + 2 * A_PANEL;  // union region start
    __nv_bfloat16* sBlo = sBhi + B_PANEL;
    float* sTile = (float*)sBhi;             // overlays B panels after MMA

    constexpr int WARPS_N = 4;
    constexpr int WM = 32;                   // 128 / 4
    constexpr int WN = OUTD / 4;             // 32 or 16
    constexpr int MFR = 2;                   // WM / 16
    constexpr int NFR = WN / 8;              // 4 or 2
    constexpr int NLD = (NFR + 1) / 2;       // ldsm x4 count for B per panel

    const int tid = threadIdx.x, wid = tid >> 5, lane = tid & 31;
    const int wm0 = (wid / WARPS_N) * WM;
    const int wn0 = (wid % WARPS_N) * WN;
    const int n0 = blockIdx.x * 128;
    const int relBase = blockIdx.y * 8;

    // --- Convert X tile -> bf16 hi/lo A panels (zero-pad OOB rows, fused ReLU)
    for (int i = tid; i < 128 * 64; i += 512) {
        int row = i >> 6, k = (i & 63) * 2;
        float2 v = make_float2(0.f, 0.f);
        int n = n0 + row;
        if (n < N_NODES) v = *(const float2*)(X + (size_t)n * 128 + k);
        if (RELU) { v.x = fmaxf(v.x, 0.f); v.y = fmaxf(v.y, 0.f); }
        __nv_bfloat16 h0 = __float2bfloat16(v.x), h1 = __float2bfloat16(v.y);
        __nv_bfloat16 l0 = __float2bfloat16(v.x - __bfloat162float(h0));
        __nv_bfloat16 l1 = __float2bfloat16(v.y - __bfloat162float(h1));
        int o = row * LDA + k;
        __nv_bfloat162 hh; hh.x = h0; hh.y = h1;
        __nv_bfloat162 ll; ll.x = l0; ll.y = l1;
        *(__nv_bfloat162*)(sAhi + o) = hh;
        *(__nv_bfloat162*)(sAlo + o) = ll;
    }

    const int lr = lane & 15;
    const int lh = lane >> 4;
    const uint32_t aHiBase = (uint32_t)__cvta_generic_to_shared(sAhi);
    const uint32_t aLoBase = (uint32_t)__cvta_generic_to_shared(sAlo);
    const uint32_t bHiBase = (uint32_t)__cvta_generic_to_shared(sBhi);
    const uint32_t bLoBase = (uint32_t)__cvta_generic_to_shared(sBlo);

    for (int ri = 0; ri < 8; ri++) {
        const int r = relBase + ri;
        __syncthreads();   // A ready (ri=0) / previous scatter done with sTile
        {   // Stage B panels: [OUTD][128] bf16 rows -> padded smem (272B rows)
            const float4* shi = (const float4*)(WThi + (size_t)r * OUTD * 128);
            const float4* slo = (const float4*)(WTlo + (size_t)r * OUTD * 128);
            float4* dhi = (float4*)sBhi;
            float4* dlo = (float4*)sBlo;
            for (int i = tid; i < OUTD * 16; i += 512) {
                int row = i >> 4, c = i & 15;
                dhi[row * 17 + c] = shi[i];
                dlo[row * 17 + c] = slo[i];
            }
        }
        __syncthreads();

        float acc[MFR][NFR][4];
        #pragma unroll
        for (int mi = 0; mi < MFR; mi++)
            #pragma unroll
            for (int ni = 0; ni < NFR; ni++)
                #pragma unroll
                for (int q = 0; q < 4; q++) acc[mi][ni][q] = 0.f;

        // Single k-loop; all 3 split products accumulate into the same acc.
        #pragma unroll
        for (int k = 0; k < 8; k++) {
            const uint32_t kofs = (uint32_t)((k * 16 + lh * 8) << 1);
            uint32_t ah[MFR][4], al[MFR][4], bh[NLD][4], bl[NLD][4];
            #pragma unroll
            for (int mi = 0; mi < MFR; mi++) {
                uint32_t rofs = (uint32_t)(((wm0 + mi * 16 + lr) * LDA) << 1) + kofs;
                ldsm_x4(ah[mi], aHiBase + rofs);
                ldsm_x4(al[mi], aLoBase + rofs);
            }
            #pragma unroll
            for (int nj = 0; nj < NLD; nj++) {
                uint32_t rofs = (uint32_t)(((wn0 + nj * 16 + lr) * LDB) << 1) + kofs;
                ldsm_x4(bh[nj], bHiBase + rofs);
                ldsm_x4(bl[nj], bLoBase + rofs);
            }
            #pragma unroll
            for (int mi = 0; mi < MFR; mi++)
                #pragma unroll
                for (int ni = 0; ni < NFR; ni++) {
                    mma_bf16(acc[mi][ni], ah[mi], bh[ni >> 1][ni & 1], bh[ni >> 1][2 + (ni & 1)]);
                    mma_bf16(acc[mi][ni], ah[mi], bl[ni >> 1][ni & 1], bl[ni >> 1][2 + (ni & 1)]);
                    mma_bf16(acc[mi][ni], al[mi], bh[ni >> 1][ni & 1], bh[ni >> 1][2 + (ni & 1)]);
                }
        }

        __syncthreads();   // all warps done reading B panels -> overlay tile

        // Epilogue: acc -> fp32 smem tile
        #pragma unroll
        for (int mi = 0; mi < MFR; mi++)
            #pragma unroll
            for (int ni = 0; ni < NFR; ni++) {
                int row = wm0 + mi * 16 + (lane >> 2);
                int col = wn0 + ni * 8 + (lane & 3) * 2;
                *(float2*)&sTile[row * LDT + col] =
                    make_float2(acc[mi][ni][0], acc[mi][ni][1]);
                *(float2*)&sTile[(row + 8) * LDT + col] =
                    make_float2(acc[mi][ni][2], acc[mi][ni][3]);
            }
        __syncthreads();   // tile visible

        // Scatter this bin's edges: accOut[dst] += tile[row] * norm
        {
            const int bin = blockIdx.x * NUM_RELS + r;
            const int off = binOff[bin];
            const int cnt = binCnt[bin];
            if (OUTD == 128) {                // 1 edge per warp, 16 warps
                for (int j = wid; j < cnt; j += 16) {
                    float4 pk = pack[off + j];
                    int row = __float_as_int(pk.x);
                    int d   = __float_as_int(pk.y);
                    float nv = pk.z;
                    float4 v = *(const float4*)&sTile[row * LDT + lane * 4];
                    v.x *= nv; v.y *= nv; v.z *= nv; v.w *= nv;
                    float* p = accOut + (size_t)d * OUTD + lane * 4;
                    asm volatile("red.global.add.v4.f32 [%0], {%1, %2, %3, %4};"
                                 :: "l"(p), "f"(v.x), "f"(v.y), "f"(v.z), "f"(v.w)
                                 : "memory");
                }
            } else {                          // OUTD == 64: 2 edges per warp
                const int sub = lane >> 4, l = lane & 15;
                for (int j = wid * 2; j < cnt; j += 32) {
                    int jj = j + sub;
                    if (jj < cnt) {
                        float4 pk = pack[off + jj];
                        int row = __float_as_int(pk.x);
                        int d   = __float_as_int(pk.y);
                        float nv = pk.z;
                        float4 v = *(const float4*)&sTile[row * LDT + l * 4];
                        v.x *= nv; v.y *= nv; v.z *= nv; v.w *= nv;
                        float* p = accOut + (size_t)d * OUTD + l * 4;
                        asm volatile("red.global.add.v4.f32 [%0], {%1, %2, %3, %4};"
                                     :: "l"(p), "f"(v.x), "f"(v.y), "f"(v.z), "f"(v.w)
                                     : "memory");
                    }
                }
            }
        }
    }
}

__global__ void zero_kernel(float4* __restrict__ p, int n4)
{
    int i = blockIdx.x * 256 + threadIdx.x;
    if (i < n4) p[i] = make_float4(0.f, 0.f, 0.f, 0.f);
}

extern "C" void kernel_launch(void* const* d_in, const int* in_sizes, int n_in,
                              void* d_out, int out_size)
{
    const float* feat = (const float*)d_in[0];
    const float* norm = (const float*)d_in[1];
    const float* W1   = (const float*)d_in[2];
    const float* W2   = (const float*)d_in[3];
    const int*   src  = (const int*)d_in[4];
    const int*   dst  = (const int*)d_in[5];
    const int*   et   = (const int*)d_in[6];
    float*       out  = (float*)d_out;

    float *H;
    int *binCnt, *binOff, *binCur;
    float4 *pack;
    __nv_bfloat16 *W1h, *W1l, *W2h, *W2l;
    cudaGetSymbolAddress((void**)&H,      g_H);
    cudaGetSymbolAddress((void**)&binCnt, g_binCnt);
    cudaGetSymbolAddress((void**)&binOff, g_binOff);
    cudaGetSymbolAddress((void**)&binCur, g_binCur);
    cudaGetSymbolAddress((void**)&pack,   g_pack);
    cudaGetSymbolAddress((void**)&W1h,    g_W1hi);
    cudaGetSymbolAddress((void**)&W1l,    g_W1lo);
    cudaGetSymbolAddress((void**)&W2h,    g_W2hi);
    cudaGetSymbolAddress((void**)&W2l,    g_W2lo);

    // smem: A panels + max(B panels, fp32 tile)
    constexpr int SMEM1 = 2 * (128 * 136 * 2)
                        + ((2 * 128 * 136 * 2 > 128 * 132 * 4) ? 2 * 128 * 136 * 2
                                                               : 128 * 132 * 4);
    constexpr int SMEM2 = 2 * (128 * 136 * 2)
                        + ((2 * 64 * 136 * 2 > 128 * 68 * 4) ? 2 * 64 * 136 * 2
                                                             : 128 * 68 * 4);
    cudaFuncSetAttribute(fused_transform_kernel<H_DIM, 0>,
                         cudaFuncAttributeMaxDynamicSharedMemorySize, SMEM1);
    cudaFuncSetAttribute(fused_transform_kernel<OUT_DIM, 1>,
                         cudaFuncAttributeMaxDynamicSharedMemorySize, SMEM2);

    // --- Edge binning by (src tile, etype): shared by both layers
    bin_reset_kernel<<<(NBINS + 255) / 256, 256>>>(binCnt, binCur);
    bin_count_kernel<<<(N_EDGES + 255) / 256, 256>>>(src, et, binCnt);
    bin_scan_kernel<<<1, 256>>>(binCnt, binOff);
    bin_fill_kernel<<<(N_EDGES + 255) / 256, 256>>>(src, dst, et, norm,
                                                    binOff, binCur, pack);

    // --- Weight pre-split / pre-transpose (tiny; L2-hot afterwards)
    prep_wt_kernel<H_DIM><<<NUM_RELS, 256>>>(W1, W1h, W1l);
    prep_wt_kernel<OUT_DIM><<<NUM_RELS, 256>>>(W2, W2h, W2l);

    // --- Layer 1: H[dst] += (feat @ W1[r])[src] * norm, fused
    {
        int n4 = N_NODES * H_DIM / 4;
        zero_kernel<<<(n4 + 255) / 256, 256>>>((float4*)H, n4);
    }
    fused_transform_kernel<H_DIM, 0><<<dim3(N_TILES, 2), 512, SMEM1>>>(
        feat, W1h, W1l, H, pack, binOff, binCnt);

    // --- Layer 2: out[dst] += (relu(H) @ W2[r])[src] * norm, fused
    cudaMemsetAsync(out, 0, (size_t)out_size * sizeof(float));
    fused_transform_kernel<OUT_DIM, 1><<<dim3(N_TILES, 2), 512, SMEM2>>>(
        H, W2h, W2l, out, pack, binOff, binCnt);
}

// round 10
// speedup vs baseline: 3.3271x; 1.0814x over previous
#include <cuda_runtime.h>
#include <cuda_bf16.h>
#include <cstdint>

#define N_NODES 50000
#define N_EDGES 800000
#define NUM_RELS 16
#define IN_DIM 128
#define H_DIM 128
#define OUT_DIM 64

#define TM 64                       // node tile
#define N_TILES 782                 // ceil(50000/64)
#define NBINS (N_TILES * NUM_RELS)  // 12512

// ---------------------------------------------------------------------------
// Scratch (device globals: allocation-free rule)
// ---------------------------------------------------------------------------
__device__ float g_H[(size_t)N_NODES * H_DIM];               // 25.6 MB
__device__ int    g_binCnt[NBINS];
__device__ int    g_binOff[NBINS];
__device__ int    g_binCur[NBINS];
__device__ float4 g_pack[N_EDGES];  // {row_in_tile, dst, norm, -} bin-ordered
__device__ __nv_bfloat16 g_W1hi[NUM_RELS * 128 * 128];
__device__ __nv_bfloat16 g_W1lo[NUM_RELS * 128 * 128];
__device__ __nv_bfloat16 g_W2hi[NUM_RELS * 64 * 128];
__device__ __nv_bfloat16 g_W2lo[NUM_RELS * 64 * 128];

// ---------------------------------------------------------------------------
// Warp-MMA helpers (baseline PTX: legal on plain sm_103 target)
// ---------------------------------------------------------------------------
__device__ __forceinline__ void ldsm_x4(uint32_t r[4], uint32_t addr) {
    asm volatile("ldmatrix.sync.aligned.m8n8.x4.shared.b16 {%0,%1,%2,%3}, [%4];"
                 : "=r"(r[0]), "=r"(r[1]), "=r"(r[2]), "=r"(r[3]) : "r"(addr));
}
__device__ __forceinline__ void mma_bf16(float c[4], const uint32_t a[4],
                                         uint32_t b0, uint32_t b1) {
    asm volatile("mma.sync.aligned.m16n8k16.row.col.f32.bf16.bf16.f32 "
                 "{%0,%1,%2,%3}, {%4,%5,%6,%7}, {%8,%9}, {%0,%1,%2,%3};"
                 : "+f"(c[0]), "+f"(c[1]), "+f"(c[2]), "+f"(c[3])
                 : "r"(a[0]), "r"(a[1]), "r"(a[2]), "r"(a[3]), "r"(b0), "r"(b1));
}

// ---------------------------------------------------------------------------
// Edge binning kernels: bin key = (src >> 6) * 16 + etype
// ---------------------------------------------------------------------------
__global__ void bin_reset_kernel(int* __restrict__ cnt, int* __restrict__ cur)
{
    int i = blockIdx.x * 256 + threadIdx.x;
    if (i < NBINS) { cnt[i] = 0; cur[i] = 0; }
}

__global__ void bin_count_kernel(const int* __restrict__ src,
                                 const int* __restrict__ et,
                                 int* __restrict__ cnt)
{
    int e = blockIdx.x * 256 + threadIdx.x;
    if (e < N_EDGES)
        atomicAdd(&cnt[(src[e] >> 6) * NUM_RELS + et[e]], 1);
}

__global__ __launch_bounds__(256)
void bin_scan_kernel(const int* __restrict__ cnt, int* __restrict__ off)
{
    __shared__ int s[256];
    const int tid = threadIdx.x;
    constexpr int PER = (NBINS + 255) / 256;  // 49
    int loc[PER];
    int base = tid * PER, sum = 0;
    #pragma unroll
    for (int i = 0; i < PER; i++) {
        int idx = base + i;
        int v = (idx < NBINS) ? cnt[idx] : 0;
        loc[i] = v; sum += v;
    }
    s[tid] = sum;
    __syncthreads();
    for (int d = 1; d < 256; d <<= 1) {
        int v = (tid >= d) ? s[tid - d] : 0;
        __syncthreads();
        s[tid] += v;
        __syncthreads();
    }
    int run = tid ? s[tid - 1] : 0;
    #pragma unroll
    for (int i = 0; i < PER; i++) {
        int idx = base + i;
        if (idx < NBINS) { off[idx] = run; run += loc[i]; }
    }
}

__global__ void bin_fill_kernel(const int* __restrict__ src,
                                const int* __restrict__ dstv,
                                const int* __restrict__ et,
                                const float* __restrict__ norm,
                                const int* __restrict__ off,
                                int* __restrict__ cur,
                                float4* __restrict__ pack)
{
    int e = blockIdx.x * 256 + threadIdx.x;
    if (e >= N_EDGES) return;
    int s = src[e];
    int bin = (s >> 6) * NUM_RELS + et[e];
    int pos = off[bin] + atomicAdd(&cur[bin], 1);
    float4 p;
    p.x = __int_as_float(s & 63);
    p.y = __int_as_float(dstv[e]);
    p.z = norm[e];
    p.w = 0.f;
    pack[pos] = p;
}

// ---------------------------------------------------------------------------
// prep: W (fp32 [R,128,OUTD]) -> W^T bf16 hi/lo as [R][n][k]
// ---------------------------------------------------------------------------
template<int OUTD>
__global__ __launch_bounds__(256)
void prep_wt_kernel(const float* __restrict__ W,
                    __nv_bfloat16* __restrict__ hi,
                    __nv_bfloat16* __restrict__ lo)
{
    int r = blockIdx.x;
    const float* Wr = W + (size_t)r * 128 * OUTD;
    __nv_bfloat16* hb = hi + (size_t)r * OUTD * 128;
    __nv_bfloat16* lb = lo + (size_t)r * OUTD * 128;
    for (int i = threadIdx.x; i < OUTD * 128; i += 256) {
        int n = i >> 7, k = i & 127;
        float x = Wr[(size_t)k * OUTD + n];
        __nv_bfloat16 h = __float2bfloat16(x);
        __nv_bfloat16 l = __float2bfloat16(x - __bfloat162float(h));
        hb[(size_t)n * 128 + k] = h;
        lb[(size_t)n * 128 + k] = l;
    }
}

// ---------------------------------------------------------------------------
// Fused transform+scatter, 256 threads (8 warps, 2x4 warp grid), TM=64.
// Smem: 104.4 KB (L1) / 69.6 KB (L2) -> 2-3 resident blocks/SM so the
// scatter / staging / MMA phases of different blocks overlap.
// ---------------------------------------------------------------------------
template<int OUTD, int RELU>
__global__ __launch_bounds__(256)
void fused_transform_kernel(const float* __restrict__ X,
                            const __nv_bfloat16* __restrict__ WThi,
                            const __nv_bfloat16* __restrict__ WTlo,
                            float* __restrict__ accOut,
                            const float4* __restrict__ pack,
                            const int* __restrict__ binOff,
                            const int* __restrict__ binCnt)
{
    constexpr int LDA = 136;                 // bf16 elems; 272B row (ldmatrix-friendly)
    constexpr int LDB = 136;
    constexpr int A_PANEL = TM * LDA;
    constexpr int B_PANEL = OUTD * LDB;
    constexpr int LDT = OUTD + 4;            // fp32 tile stride

    extern __shared__ __nv_bfloat16 sm[];
    __nv_bfloat16* sAhi = sm;
    __nv_bfloat16* sAlo = sm + A_PANEL;
    __nv_bfloat16* sBhi = sm + 2 * A_PANEL;  // union region start
    __nv_bfloat16* sBlo = sBhi + B_PANEL;
    float* sTile = (float*)sBhi;             // overlays B panels after MMA

    constexpr int WARPS_N = 4;
    constexpr int WM = 32;                   // TM / 2
    constexpr int WN = OUTD / 4;             // 32 or 16
    constexpr int MFR = 2;                   // WM / 16
    constexpr int NFR = WN / 8;              // 4 or 2
    constexpr int NLD = (NFR + 1) / 2;

    const int tid = threadIdx.x, wid = tid >> 5, lane = tid & 31;
    const int wm0 = (wid / WARPS_N) * WM;
    const int wn0 = (wid % WARPS_N) * WN;
    const int n0 = blockIdx.x * TM;
    const int relBase = blockIdx.y * 8;

    // --- Convert X tile -> bf16 hi/lo A panels (zero-pad OOB rows, fused ReLU)
    for (int i = tid; i < TM * 64; i += 256) {
        int row = i >> 6, k = (i & 63) * 2;
        float2 v = make_float2(0.f, 0.f);
        int n = n0 + row;
        if (n < N_NODES) v = *(const float2*)(X + (size_t)n * 128 + k);
        if (RELU) { v.x = fmaxf(v.x, 0.f); v.y = fmaxf(v.y, 0.f); }
        __nv_bfloat16 h0 = __float2bfloat16(v.x), h1 = __float2bfloat16(v.y);
        __nv_bfloat16 l0 = __float2bfloat16(v.x - __bfloat162float(h0));
        __nv_bfloat16 l1 = __float2bfloat16(v.y - __bfloat162float(h1));
        int o = row * LDA + k;
        __nv_bfloat162 hh; hh.x = h0; hh.y = h1;
        __nv_bfloat162 ll; ll.x = l0; ll.y = l1;
        *(__nv_bfloat162*)(sAhi + o) = hh;
        *(__nv_bfloat162*)(sAlo + o) = ll;
    }

    const int lr = lane & 15;
    const int lh = lane >> 4;
    const uint32_t aHiBase = (uint32_t)__cvta_generic_to_shared(sAhi);
    const uint32_t aLoBase = (uint32_t)__cvta_generic_to_shared(sAlo);
    const uint32_t bHiBase = (uint32_t)__cvta_generic_to_shared(sBhi);
    const uint32_t bLoBase = (uint32_t)__cvta_generic_to_shared(sBlo);

    for (int ri = 0; ri < 8; ri++) {
        const int r = relBase + ri;
        __syncthreads();   // A ready (ri=0) / previous scatter done with sTile
        {   // Stage B panels: [OUTD][128] bf16 rows -> padded smem (272B rows)
            const float4* shi = (const float4*)(WThi + (size_t)r * OUTD * 128);
            const float4* slo = (const float4*)(WTlo + (size_t)r * OUTD * 128);
            float4* dhi = (float4*)sBhi;
            float4* dlo = (float4*)sBlo;
            for (int i = tid; i < OUTD * 16; i += 256) {
                int row = i >> 4, c = i & 15;
                dhi[row * 17 + c] = shi[i];
                dlo[row * 17 + c] = slo[i];
            }
        }
        __syncthreads();

        float acc[MFR][NFR][4];
        #pragma unroll
        for (int mi = 0; mi < MFR; mi++)
            #pragma unroll
            for (int ni = 0; ni < NFR; ni++)
                #pragma unroll
                for (int q = 0; q < 4; q++) acc[mi][ni][q] = 0.f;

        // Single k-loop; all 3 split products accumulate into the same acc.
        #pragma unroll
        for (int k = 0; k < 8; k++) {
            const uint32_t kofs = (uint32_t)((k * 16 + lh * 8) << 1);
            uint32_t ah[MFR][4], al[MFR][4], bh[NLD][4], bl[NLD][4];
            #pragma unroll
            for (int mi = 0; mi < MFR; mi++) {
                uint32_t rofs = (uint32_t)(((wm0 + mi * 16 + lr) * LDA) << 1) + kofs;
                ldsm_x4(ah[mi], aHiBase + rofs);
                ldsm_x4(al[mi], aLoBase + rofs);
            }
            #pragma unroll
            for (int nj = 0; nj < NLD; nj++) {
                uint32_t rofs = (uint32_t)(((wn0 + nj * 16 + lr) * LDB) << 1) + kofs;
                ldsm_x4(bh[nj], bHiBase + rofs);
                ldsm_x4(bl[nj], bLoBase + rofs);
            }
            #pragma unroll
            for (int mi = 0; mi < MFR; mi++)
                #pragma unroll
                for (int ni = 0; ni < NFR; ni++) {
                    mma_bf16(acc[mi][ni], ah[mi], bh[ni >> 1][ni & 1], bh[ni >> 1][2 + (ni & 1)]);
                    mma_bf16(acc[mi][ni], ah[mi], bl[ni >> 1][ni & 1], bl[ni >> 1][2 + (ni & 1)]);
                    mma_bf16(acc[mi][ni], al[mi], bh[ni >> 1][ni & 1], bh[ni >> 1][2 + (ni & 1)]);
                }
        }

        __syncthreads();   // all warps done reading B panels -> overlay tile

        // Epilogue: acc -> fp32 smem tile
        #pragma unroll
        for (int mi = 0; mi < MFR; mi++)
            #pragma unroll
            for (int ni = 0; ni < NFR; ni++) {
                int row = wm0 + mi * 16 + (lane >> 2);
                int col = wn0 + ni * 8 + (lane & 3) * 2;
                *(float2*)&sTile[row * LDT + col] =
                    make_float2(acc[mi][ni][0], acc[mi][ni][1]);
                *(float2*)&sTile[(row + 8) * LDT + col] =
                    make_float2(acc[mi][ni][2], acc[mi][ni][3]);
            }
        __syncthreads();   // tile visible

        // Scatter this bin's edges: accOut[dst] += tile[row] * norm
        {
            const int bin = blockIdx.x * NUM_RELS + r;
            const int off = binOff[bin];
            const int cnt = binCnt[bin];
            if (OUTD == 128) {                // 1 edge per warp
                for (int j = wid; j < cnt; j += 8) {
                    float4 pk = pack[off + j];
                    int row = __float_as_int(pk.x);
                    int d   = __float_as_int(pk.y);
                    float nv = pk.z;
                    float4 v = *(const float4*)&sTile[row * LDT + lane * 4];
                    v.x *= nv; v.y *= nv; v.z *= nv; v.w *= nv;
                    float* p = accOut + (size_t)d * OUTD + lane * 4;
                    asm volatile("red.global.add.v4.f32 [%0], {%1, %2, %3, %4};"
                                 :: "l"(p), "f"(v.x), "f"(v.y), "f"(v.z), "f"(v.w)
                                 : "memory");
                }
            } else {                          // OUTD == 64: 2 edges per warp
                const int sub = lane >> 4, l = lane & 15;
                for (int j = wid * 2; j < cnt; j += 16) {
                    int jj = j + sub;
                    if (jj < cnt) {
                        float4 pk = pack[off + jj];
                        int row = __float_as_int(pk.x);
                        int d   = __float_as_int(pk.y);
                        float nv = pk.z;
                        float4 v = *(const float4*)&sTile[row * LDT + l * 4];
                        v.x *= nv; v.y *= nv; v.z *= nv; v.w *= nv;
                        float* p = accOut + (size_t)d * OUTD + l * 4;
                        asm volatile("red.global.add.v4.f32 [%0], {%1, %2, %3, %4};"
                                     :: "l"(p), "f"(v.x), "f"(v.y), "f"(v.z), "f"(v.w)
                                     : "memory");
                    }
                }
            }
        }
    }
}

__global__ void zero_kernel(float4* __restrict__ p, int n4)
{
    int i = blockIdx.x * 256 + threadIdx.x;
    if (i < n4) p[i] = make_float4(0.f, 0.f, 0.f, 0.f);
}

extern "C" void kernel_launch(void* const* d_in, const int* in_sizes, int n_in,
                              void* d_out, int out_size)
{
    const float* feat = (const float*)d_in[0];
    const float* norm = (const float*)d_in[1];
    const float* W1   = (const float*)d_in[2];
    const float* W2   = (const float*)d_in[3];
    const int*   src  = (const int*)d_in[4];
    const int*   dst  = (const int*)d_in[5];
    const int*   et   = (const int*)d_in[6];
    float*       out  = (float*)d_out;

    float *H;
    int *binCnt, *binOff, *binCur;
    float4 *pack;
    __nv_bfloat16 *W1h, *W1l, *W2h, *W2l;
    cudaGetSymbolAddress((void**)&H,      g_H);
    cudaGetSymbolAddress((void**)&binCnt, g_binCnt);
    cudaGetSymbolAddress((void**)&binOff, g_binOff);
    cudaGetSymbolAddress((void**)&binCur, g_binCur);
    cudaGetSymbolAddress((void**)&pack,   g_pack);
    cudaGetSymbolAddress((void**)&W1h,    g_W1hi);
    cudaGetSymbolAddress((void**)&W1l,    g_W1lo);
    cudaGetSymbolAddress((void**)&W2h,    g_W2hi);
    cudaGetSymbolAddress((void**)&W2l,    g_W2lo);

    // smem: A panels + max(B panels, fp32 tile)
    constexpr int SMEM1 = 2 * (TM * 136 * 2)
                        + ((2 * 128 * 136 * 2 > TM * 132 * 4) ? 2 * 128 * 136 * 2
                                                              : TM * 132 * 4);
    constexpr int SMEM2 = 2 * (TM * 136 * 2)
                        + ((2 * 64 * 136 * 2 > TM * 68 * 4) ? 2 * 64 * 136 * 2
                                                            : TM * 68 * 4);
    cudaFuncSetAttribute(fused_transform_kernel<H_DIM, 0>,
                         cudaFuncAttributeMaxDynamicSharedMemorySize, SMEM1);
    cudaFuncSetAttribute(fused_transform_kernel<OUT_DIM, 1>,
                         cudaFuncAttributeMaxDynamicSharedMemorySize, SMEM2);

    // --- Edge binning by (src tile, etype): shared by both layers
    bin_reset_kernel<<<(NBINS + 255) / 256, 256>>>(binCnt, binCur);
    bin_count_kernel<<<(N_EDGES + 255) / 256, 256>>>(src, et, binCnt);
    bin_scan_kernel<<<1, 256>>>(binCnt, binOff);
    bin_fill_kernel<<<(N_EDGES + 255) / 256, 256>>>(src, dst, et, norm,
                                                    binOff, binCur, pack);

    // --- Weight pre-split / pre-transpose (tiny; L2-hot afterwards)
    prep_wt_kernel<H_DIM><<<NUM_RELS, 256>>>(W1, W1h, W1l);
    prep_wt_kernel<OUT_DIM><<<NUM_RELS, 256>>>(W2, W2h, W2l);

    // --- Layer 1: H[dst] += (feat @ W1[r])[src] * norm, fused
    {
        int n4 = N_NODES * H_DIM / 4;
        zero_kernel<<<(n4 + 255) / 256, 256>>>((float4*)H, n4);
    }
    fused_transform_kernel<H_DIM, 0><<<dim3(N_TILES, 2), 256, SMEM1>>>(
        feat, W1h, W1l, H, pack, binOff, binCnt);

    // --- Layer 2: out[dst] += (relu(H) @ W2[r])[src] * norm, fused
    cudaMemsetAsync(out, 0, (size_t)out_size * sizeof(float));
    fused_transform_kernel<OUT_DIM, 1><<<dim3(N_TILES, 2), 256, SMEM2>>>(
        H, W2h, W2l, out, pack, binOff, binCnt);
}

// round 13
// speedup vs baseline: 3.5132x; 1.0559x over previous
#include <cuda_runtime.h>
#include <cuda_bf16.h>
#include <cstdint>

#define N_NODES 50000
#define N_EDGES 800000
#define NUM_RELS 16
#define IN_DIM 128
#define H_DIM 128
#define OUT_DIM 64

#define TM 64                        // node tile
#define N_TILES 782                  // ceil(50000/64)
#define NPAD (N_TILES * 64)          // 50048
#define NBINS (N_TILES * NUM_RELS)   // 12512
#define XBLKS ((NPAD * 64) / 256)    // 12512 prep blocks
#define HZ4 ((N_NODES * H_DIM) / 4)  // float4 count of H
#define HBLKS ((HZ4 + 255) / 256)    // 6250

// ---------------------------------------------------------------------------
// Scratch (device globals: allocation-free rule)
// ---------------------------------------------------------------------------
__device__ float g_H[(size_t)N_NODES * H_DIM];      // 25.6 MB
__device__ int    g_binCnt[NBINS];
__device__ int    g_binOff[NBINS];
__device__ int    g_binCur[NBINS];
__device__ float4 g_pack[N_EDGES];                  // {row, dst, norm, -}
// Pre-split images, plain layout: row = 256 bf16 = [0:128) hi | [128:256) lo
__device__ __nv_bfloat16 g_X [(size_t)NPAD * 256];  // X or H split, 25.6 MB
__device__ __nv_bfloat16 g_W1[NUM_RELS * 128 * 256];// W1^T split (n-major), 1 MB
__device__ __nv_bfloat16 g_W2[NUM_RELS * 64 * 256]; // W2^T split, 0.5 MB

// ---------------------------------------------------------------------------
// Warp-MMA helpers (baseline PTX: legal on plain sm_103 target)
// ---------------------------------------------------------------------------
__device__ __forceinline__ void ldsm_x4(uint32_t r[4], uint32_t addr) {
    asm volatile("ldmatrix.sync.aligned.m8n8.x4.shared.b16 {%0,%1,%2,%3}, [%4];"
                 : "=r"(r[0]), "=r"(r[1]), "=r"(r[2]), "=r"(r[3]) : "r"(addr));
}
__device__ __forceinline__ void mma_bf16(float c[4], const uint32_t a[4],
                                         uint32_t b0, uint32_t b1) {
    asm volatile("mma.sync.aligned.m16n8k16.row.col.f32.bf16.bf16.f32 "
                 "{%0,%1,%2,%3}, {%4,%5,%6,%7}, {%8,%9}, {%0,%1,%2,%3};"
                 : "+f"(c[0]), "+f"(c[1]), "+f"(c[2]), "+f"(c[3])
                 : "r"(a[0]), "r"(a[1]), "r"(a[2]), "r"(a[3]), "r"(b0), "r"(b1));
}

// ---------------------------------------------------------------------------
// combo prep: W1+W2 -> split W^T images (n-major rows of 256: hi|lo);
// also resets bin counters. grid (NUM_RELS, 2): y==0 -> W1 (+reset), y==1 -> W2.
// ---------------------------------------------------------------------------
__global__ __launch_bounds__(256)
void combo_prep_kernel(const float* __restrict__ W1, const float* __restrict__ W2,
                       __nv_bfloat16* __restrict__ w1img,
                       __nv_bfloat16* __restrict__ w2img,
                       int* __restrict__ cnt, int* __restrict__ cur)
{
    const int r = blockIdx.x, tid = threadIdx.x;
    const int OUTD = blockIdx.y == 0 ? 128 : 64;
    const float* Wr = (blockIdx.y == 0 ? W1 : W2) + (size_t)r * 128 * OUTD;
    __nv_bfloat16* img = (blockIdx.y == 0 ? w1img : w2img) + (size_t)r * OUTD * 256;
    for (int i = tid; i < OUTD * 128; i += 256) {
        int n = i >> 7, k = i & 127;
        float x = Wr[(size_t)k * OUTD + n];
        __nv_bfloat16 h = __float2bfloat16(x);
        __nv_bfloat16 l = __float2bfloat16(x - __bfloat162float(h));
        img[n * 256 + k] = h;
        img[n * 256 + 128 + k] = l;
    }
    if (blockIdx.y == 0) {
        for (int i = r * 256 + tid; i < NBINS; i += NUM_RELS * 256) {
            cnt[i] = 0; cur[i] = 0;
        }
    }
}

// ---------------------------------------------------------------------------
// Edge binning: key = (src >> 6) * 16 + etype, row = src & 63  (R10-proven)
// ---------------------------------------------------------------------------
__global__ void bin_count_kernel(const int* __restrict__ src,
                                 const int* __restrict__ et,
                                 int* __restrict__ cnt)
{
    int e = blockIdx.x * 256 + threadIdx.x;
    if (e < N_EDGES)
        atomicAdd(&cnt[(src[e] >> 6) * NUM_RELS + et[e]], 1);
}

__global__ __launch_bounds__(256)
void bin_scan_kernel(const int* __restrict__ cnt, int* __restrict__ off)
{
    __shared__ int s[256];
    const int tid = threadIdx.x;
    constexpr int PER = (NBINS + 255) / 256;  // 49
    int loc[PER];
    int base = tid * PER, sum = 0;
    #pragma unroll
    for (int i = 0; i < PER; i++) {
        int idx = base + i;
        int v = (idx < NBINS) ? cnt[idx] : 0;
        loc[i] = v; sum += v;
    }
    s[tid] = sum;
    __syncthreads();
    for (int d = 1; d < 256; d <<= 1) {
        int v = (tid >= d) ? s[tid - d] : 0;
        __syncthreads();
        s[tid] += v;
        __syncthreads();
    }
    int run = tid ? s[tid - 1] : 0;
    #pragma unroll
    for (int i = 0; i < PER; i++) {
        int idx = base + i;
        if (idx < NBINS) { off[idx] = run; run += loc[i]; }
    }
}

__global__ void bin_fill_kernel(const int* __restrict__ src,
                                const int* __restrict__ dstv,
                                const int* __restrict__ et,
                                const float* __restrict__ norm,
                                const int* __restrict__ off,
                                int* __restrict__ cur,
                                float4* __restrict__ pack)
{
    int e = blockIdx.x * 256 + threadIdx.x;
    if (e >= N_EDGES) return;
    int s = src[e];
    int bin = (s >> 6) * NUM_RELS + et[e];
    int pos = off[bin] + atomicAdd(&cur[bin], 1);
    float4 p;
    p.x = __int_as_float(s & 63);
    p.y = __int_as_float(dstv[e]);
    p.z = norm[e];
    p.w = 0.f;
    pack[pos] = p;
}

// ---------------------------------------------------------------------------
// prep_x: fp32 [N,128] -> split hi/lo image (optional fused ReLU); extra
// grid blocks zero an accumulator buffer.
// ---------------------------------------------------------------------------
template<int RELU>
__global__ __launch_bounds__(256)
void prep_x_kernel(const float* __restrict__ X, __nv_bfloat16* __restrict__ img,
                   float4* __restrict__ zbuf, int zn4)
{
    const int b = blockIdx.x;
    if (b < XBLKS) {
        int i = b * 256 + threadIdx.x;       // < NPAD * 64
        int n = i >> 6, k = (i & 63) * 2;
        float2 v = make_float2(0.f, 0.f);
        if (n < N_NODES) v = *(const float2*)(X + (size_t)n * 128 + k);
        if (RELU) { v.x = fmaxf(v.x, 0.f); v.y = fmaxf(v.y, 0.f); }
        __nv_bfloat16 h0 = __float2bfloat16(v.x), h1 = __float2bfloat16(v.y);
        __nv_bfloat16 l0 = __float2bfloat16(v.x - __bfloat162float(h0));
        __nv_bfloat16 l1 = __float2bfloat16(v.y - __bfloat162float(h1));
        size_t o = (size_t)n * 256 + k;
        __nv_bfloat162 hh; hh.x = h0; hh.y = h1;
        __nv_bfloat162 ll; ll.x = l0; ll.y = l1;
        *(__nv_bfloat162*)&img[o] = hh;
        *(__nv_bfloat162*)&img[o + 128] = ll;
    } else {
        int i = (b - XBLKS) * 256 + threadIdx.x;
        if (i < zn4) zbuf[i] = make_float4(0.f, 0.f, 0.f, 0.f);
    }
}

// ---------------------------------------------------------------------------
// Fused transform+scatter, rel-outer / tile-inner (R10 mechanisms):
//   block = (chunk, rel). Stage W[rel] panels ONCE (padded-136 layout),
//   then stream node tiles: stage A (float4 copy from split image), MMA
//   (R10 inner loop), epilogue into fp32 tile overlaying the A panels,
//   scatter the (tile, rel) edge bin with red.global.add.v4.
// ---------------------------------------------------------------------------
template<int OUTD>
__global__ __launch_bounds__(256)
void fused_transform_kernel(const __nv_bfloat16* __restrict__ Ximg,
                            const __nv_bfloat16* __restrict__ Wimg,
                            float* __restrict__ accOut,
                            const float4* __restrict__ pack,
                            const int* __restrict__ binOff,
                            const int* __restrict__ binCnt)
{
    constexpr int LDA = 136;                 // padded bf16 stride (R10-proven)
    constexpr int LDB = 136;
    constexpr int A_PANEL = TM * LDA;        // elems
    constexpr int B_PANEL = OUTD * LDB;
    constexpr int LDT = OUTD + 4;            // fp32 tile stride

    extern __shared__ __nv_bfloat16 sm[];
    __nv_bfloat16* sAhi = sm;
    __nv_bfloat16* sAlo = sm + A_PANEL;
    __nv_bfloat16* sBhi = sm + 2 * A_PANEL;
    __nv_bfloat16* sBlo = sBhi + B_PANEL;
    float* sTile = (float*)sm;               // overlays A panels after MMA

    constexpr int WARPS_N = 4;
    constexpr int WM = 32;                   // TM / 2
    constexpr int WN = OUTD / 4;             // 32 or 16
    constexpr int MFR = 2;                   // WM / 16
    constexpr int NFR = WN / 8;              // 4 or 2
    constexpr int NLD = (NFR + 1) / 2;

    const int tid = threadIdx.x, wid = tid >> 5, lane = tid & 31;
    const int wm0 = (wid / WARPS_N) * WM;
    const int wn0 = (wid % WARPS_N) * WN;
    const int rel = blockIdx.y;
    const int lr = lane & 15, lh = lane >> 4;

    const uint32_t aHiBase = (uint32_t)__cvta_generic_to_shared(sAhi);
    const uint32_t aLoBase = (uint32_t)__cvta_generic_to_shared(sAlo);
    const uint32_t bHiBase = (uint32_t)__cvta_generic_to_shared(sBhi);
    const uint32_t bLoBase = (uint32_t)__cvta_generic_to_shared(sBlo);

    // ---- Stage B panels ONCE: image rows (256 bf16 = 32 float4: hi|lo)
    {
        const __nv_bfloat16* gW = Wimg + (size_t)rel * OUTD * 256;
        for (int i = tid; i < OUTD * 32; i += 256) {
            int row = i >> 5, c = i & 31;
            float4 v = *(const float4*)(gW + row * 256 + c * 8);
            if (c < 16) *(float4*)&sBhi[row * LDB + c * 8] = v;
            else        *(float4*)&sBlo[row * LDB + (c - 16) * 8] = v;
        }
    }

    for (int t = blockIdx.x; t < N_TILES; t += gridDim.x) {
        __syncthreads();   // prior scatter done -> A/tile region free
        // ---- Stage A panels for tile t (float4 copy from split image)
        {
            const __nv_bfloat16* gA = Ximg + (size_t)t * TM * 256;
            for (int i = tid; i < TM * 32; i += 256) {
                int row = i >> 5, c = i & 31;
                float4 v = *(const float4*)(gA + row * 256 + c * 8);
                if (c < 16) *(float4*)&sAhi[row * LDA + c * 8] = v;
                else        *(float4*)&sAlo[row * LDA + (c - 16) * 8] = v;
            }
        }
        __syncthreads();   // A (and B on first iter) visible

        // ---- MMA: tile = A @ W^T, split bf16, 3 products into one acc
        float acc[MFR][NFR][4];
        #pragma unroll
        for (int mi = 0; mi < MFR; mi++)
            #pragma unroll
            for (int ni = 0; ni < NFR; ni++)
                #pragma unroll
                for (int q = 0; q < 4; q++) acc[mi][ni][q] = 0.f;

        #pragma unroll
        for (int k = 0; k < 8; k++) {
            const uint32_t kofs = (uint32_t)((k * 16 + lh * 8) << 1);
            uint32_t ah[MFR][4], al[MFR][4], bh[NLD][4], bl[NLD][4];
            #pragma unroll
            for (int mi = 0; mi < MFR; mi++) {
                uint32_t rofs = (uint32_t)(((wm0 + mi * 16 + lr) * LDA) << 1) + kofs;
                ldsm_x4(ah[mi], aHiBase + rofs);
                ldsm_x4(al[mi], aLoBase + rofs);
            }
            #pragma unroll
            for (int nj = 0; nj < NLD; nj++) {
                uint32_t rofs = (uint32_t)(((wn0 + nj * 16 + lr) * LDB) << 1) + kofs;
                ldsm_x4(bh[nj], bHiBase + rofs);
                ldsm_x4(bl[nj], bLoBase + rofs);
            }
            #pragma unroll
            for (int mi = 0; mi < MFR; mi++)
                #pragma unroll
                for (int ni = 0; ni < NFR; ni++) {
                    mma_bf16(acc[mi][ni], ah[mi], bh[ni >> 1][ni & 1], bh[ni >> 1][2 + (ni & 1)]);
                    mma_bf16(acc[mi][ni], ah[mi], bl[ni >> 1][ni & 1], bl[ni >> 1][2 + (ni & 1)]);
                    mma_bf16(acc[mi][ni], al[mi], bh[ni >> 1][ni & 1], bh[ni >> 1][2 + (ni & 1)]);
                }
        }
        __syncthreads();   // all warps done reading A -> overlay tile

        // ---- Epilogue: acc -> fp32 smem tile (overlaying A panels)
        #pragma unroll
        for (int mi = 0; mi < MFR; mi++)
            #pragma unroll
            for (int ni = 0; ni < NFR; ni++) {
                int row = wm0 + mi * 16 + (lane >> 2);
                int col = wn0 + ni * 8 + (lane & 3) * 2;
                *(float2*)&sTile[row * LDT + col] =
                    make_float2(acc[mi][ni][0], acc[mi][ni][1]);
                *(float2*)&sTile[(row + 8) * LDT + col] =
                    make_float2(acc[mi][ni][2], acc[mi][ni][3]);
            }
        __syncthreads();   // tile visible

        // ---- Scatter bin (t, rel): accOut[dst] += tile[row] * norm
        {
            const int bin = t * NUM_RELS + rel;
            const int off = binOff[bin];
            const int cnt = binCnt[bin];
            if (OUTD == 128) {               // 1 edge per warp
                for (int j = wid; j < cnt; j += 8) {
                    float4 pk = pack[off + j];
                    int row = __float_as_int(pk.x);
                    int d   = __float_as_int(pk.y);
                    float nv = pk.z;
                    float4 v = *(const float4*)&sTile[row * LDT + lane * 4];
                    v.x *= nv; v.y *= nv; v.z *= nv; v.w *= nv;
                    float* p = accOut + (size_t)d * OUTD + lane * 4;
                    asm volatile("red.global.add.v4.f32 [%0], {%1, %2, %3, %4};"
                                 :: "l"(p), "f"(v.x), "f"(v.y), "f"(v.z), "f"(v.w)
                                 : "memory");
                }
            } else {                         // OUTD==64: 2 edges per warp
                const int sub = lane >> 4, l = lane & 15;
                for (int j = wid * 2; j < cnt; j += 16) {
                    int jj = j + sub;
                    if (jj < cnt) {
                        float4 pk = pack[off + jj];
                        int row = __float_as_int(pk.x);
                        int d   = __float_as_int(pk.y);
                        float nv = pk.z;
                        float4 v = *(const float4*)&sTile[row * LDT + l * 4];
                        v.x *= nv; v.y *= nv; v.z *= nv; v.w *= nv;
                        float* p = accOut + (size_t)d * OUTD + l * 4;
                        asm volatile("red.global.add.v4.f32 [%0], {%1, %2, %3, %4};"
                                     :: "l"(p), "f"(v.x), "f"(v.y), "f"(v.z), "f"(v.w)
                                     : "memory");
                    }
                }
            }
        }
    }
}

extern "C" void kernel_launch(void* const* d_in, const int* in_sizes, int n_in,
                              void* d_out, int out_size)
{
    const float* feat = (const float*)d_in[0];
    const float* norm = (const float*)d_in[1];
    const float* W1   = (const float*)d_in[2];
    const float* W2   = (const float*)d_in[3];
    const int*   src  = (const int*)d_in[4];
    const int*   dst  = (const int*)d_in[5];
    const int*   et   = (const int*)d_in[6];
    float*       out  = (float*)d_out;

    float *H;
    int *binCnt, *binOff, *binCur;
    float4 *pack;
    __nv_bfloat16 *Ximg, *W1img, *W2img;
    cudaGetSymbolAddress((void**)&H,      g_H);
    cudaGetSymbolAddress((void**)&binCnt, g_binCnt);
    cudaGetSymbolAddress((void**)&binOff, g_binOff);
    cudaGetSymbolAddress((void**)&binCur, g_binCur);
    cudaGetSymbolAddress((void**)&pack,   g_pack);
    cudaGetSymbolAddress((void**)&Ximg,   g_X);
    cudaGetSymbolAddress((void**)&W1img,  g_W1);
    cudaGetSymbolAddress((void**)&W2img,  g_W2);

    // smem: A panels (hi+lo, also fp32 tile overlay) + B panels (hi+lo)
    constexpr int SMEM1 = (2 * TM * 136 + 2 * 128 * 136) * 2;  // 104448
    constexpr int SMEM2 = (2 * TM * 136 + 2 * 64 * 136) * 2;   //  69632
    cudaFuncSetAttribute(fused_transform_kernel<H_DIM>,
                         cudaFuncAttributeMaxDynamicSharedMemorySize, SMEM1);
    cudaFuncSetAttribute(fused_transform_kernel<OUT_DIM>,
                         cudaFuncAttributeMaxDynamicSharedMemorySize, SMEM2);

    // 1: weight prep + bin reset
    combo_prep_kernel<<<dim3(NUM_RELS, 2), 256>>>(W1, W2, W1img, W2img,
                                                  binCnt, binCur);
    // 2-4: edge binning (shared by both layers)
    bin_count_kernel<<<(N_EDGES + 255) / 256, 256>>>(src, et, binCnt);
    bin_scan_kernel<<<1, 256>>>(binCnt, binOff);
    bin_fill_kernel<<<(N_EDGES + 255) / 256, 256>>>(src, dst, et, norm,
                                                    binOff, binCur, pack);
    // 5: split feat -> image, zero H
    prep_x_kernel<0><<<XBLKS + HBLKS, 256>>>(feat, Ximg, (float4*)H, HZ4);
    // 6: layer 1 fused (ncu -s 5 -c 1 captures this launch); 19*16=304 blocks
    fused_transform_kernel<H_DIM><<<dim3(19, NUM_RELS), 256, SMEM1>>>(
        Ximg, W1img, H, pack, binOff, binCnt);
    // 7: split relu(H) -> image
    prep_x_kernel<1><<<XBLKS, 256>>>(H, Ximg, nullptr, 0);
    // 8: zero output (harness poisons to 0xAA)
    cudaMemsetAsync(out, 0, (size_t)out_size * sizeof(float));
    // 9: layer 2 fused; 28*16=448 blocks (3 blocks/SM capacity)
    fused_transform_kernel<OUT_DIM><<<dim3(28, NUM_RELS), 256, SMEM2>>>(
        Ximg, W2img, out, pack, binOff, binCnt);
}

// round 14
// speedup vs baseline: 3.6621x; 1.0424x over previous
#include <cuda_runtime.h>
#include <cuda_bf16.h>
#include <cstdint>

#define N_NODES 50000
#define N_EDGES 800000
#define NUM_RELS 16
#define IN_DIM 128
#define H_DIM 128
#define OUT_DIM 64

#define TM 64                        // node tile
#define N_TILES 782                  // ceil(50000/64)
#define NPAD (N_TILES * 64)          // 50048
#define NBINS (N_TILES * NUM_RELS)   // 12512
#define BIN_CAP 160                  // fixed bin capacity (Poisson(64) tail ~1e-25)
#define XBLKS ((NPAD * 64) / 256)    // 12512 prep blocks
#define HZ4 ((N_NODES * H_DIM) / 4)  // float4 count of H
#define HBLKS ((HZ4 + 255) / 256)    // 6250

// ---------------------------------------------------------------------------
// Scratch (device globals: allocation-free rule)
// ---------------------------------------------------------------------------
__device__ float g_H[(size_t)N_NODES * H_DIM];      // 25.6 MB
__device__ int    g_binCur[NBINS];
__device__ float4 g_pack[(size_t)NBINS * BIN_CAP];  // 32 MB, slot = bin*CAP+pos
// Pre-split images, plain layout: row = 256 bf16 = [0:128) hi | [128:256) lo
__device__ __nv_bfloat16 g_X [(size_t)NPAD * 256];  // X or H split, 25.6 MB
__device__ __nv_bfloat16 g_W1[NUM_RELS * 128 * 256];// W1^T split (n-major), 1 MB
__device__ __nv_bfloat16 g_W2[NUM_RELS * 64 * 256]; // W2^T split, 0.5 MB

// ---------------------------------------------------------------------------
// Warp-MMA helpers (baseline PTX: legal on plain sm_103 target)
// ---------------------------------------------------------------------------
__device__ __forceinline__ void ldsm_x4(uint32_t r[4], uint32_t addr) {
    asm volatile("ldmatrix.sync.aligned.m8n8.x4.shared.b16 {%0,%1,%2,%3}, [%4];"
                 : "=r"(r[0]), "=r"(r[1]), "=r"(r[2]), "=r"(r[3]) : "r"(addr));
}
__device__ __forceinline__ void mma_bf16(float c[4], const uint32_t a[4],
                                         uint32_t b0, uint32_t b1) {
    asm volatile("mma.sync.aligned.m16n8k16.row.col.f32.bf16.bf16.f32 "
                 "{%0,%1,%2,%3}, {%4,%5,%6,%7}, {%8,%9}, {%0,%1,%2,%3};"
                 : "+f"(c[0]), "+f"(c[1]), "+f"(c[2]), "+f"(c[3])
                 : "r"(a[0]), "r"(a[1]), "r"(a[2]), "r"(a[3]), "r"(b0), "r"(b1));
}

// ---------------------------------------------------------------------------
// combo prep: W1+W2 -> split W^T images (n-major rows of 256: hi|lo);
// also zeroes bin cursors. grid (NUM_RELS, 2): y==0 -> W1 (+reset), y==1 -> W2.
// ---------------------------------------------------------------------------
__global__ __launch_bounds__(256)
void combo_prep_kernel(const float* __restrict__ W1, const float* __restrict__ W2,
                       __nv_bfloat16* __restrict__ w1img,
                       __nv_bfloat16* __restrict__ w2img,
                       int* __restrict__ cur)
{
    const int r = blockIdx.x, tid = threadIdx.x;
    const int OUTD = blockIdx.y == 0 ? 128 : 64;
    const float* Wr = (blockIdx.y == 0 ? W1 : W2) + (size_t)r * 128 * OUTD;
    __nv_bfloat16* img = (blockIdx.y == 0 ? w1img : w2img) + (size_t)r * OUTD * 256;
    for (int i = tid; i < OUTD * 128; i += 256) {
        int n = i >> 7, k = i & 127;
        float x = Wr[(size_t)k * OUTD + n];
        __nv_bfloat16 h = __float2bfloat16(x);
        __nv_bfloat16 l = __float2bfloat16(x - __bfloat162float(h));
        img[n * 256 + k] = h;
        img[n * 256 + 128 + k] = l;
    }
    if (blockIdx.y == 0) {
        for (int i = r * 256 + tid; i < NBINS; i += NUM_RELS * 256)
            cur[i] = 0;
    }
}

// ---------------------------------------------------------------------------
// Single-pass edge binning: key = (src>>6)*16 + etype, slot = bin*CAP + pos.
// ---------------------------------------------------------------------------
__global__ void bin_fill_kernel(const int* __restrict__ src,
                                const int* __restrict__ dstv,
                                const int* __restrict__ et,
                                const float* __restrict__ norm,
                                int* __restrict__ cur,
                                float4* __restrict__ pack)
{
    int e = blockIdx.x * 256 + threadIdx.x;
    if (e >= N_EDGES) return;
    int s = src[e];
    int bin = (s >> 6) * NUM_RELS + et[e];
    int pos = atomicAdd(&cur[bin], 1);
    if (pos < BIN_CAP) {
        float4 p;
        p.x = __int_as_float(s & 63);
        p.y = __int_as_float(dstv[e]);
        p.z = norm[e];
        p.w = 0.f;
        pack[(size_t)bin * BIN_CAP + pos] = p;
    }
}

// ---------------------------------------------------------------------------
// prep_x: fp32 [N,128] -> split hi/lo image (optional fused ReLU); extra
// grid blocks zero an accumulator buffer.
// ---------------------------------------------------------------------------
template<int RELU>
__global__ __launch_bounds__(256)
void prep_x_kernel(const float* __restrict__ X, __nv_bfloat16* __restrict__ img,
                   float4* __restrict__ zbuf, int zn4)
{
    const int b = blockIdx.x;
    if (b < XBLKS) {
        int i = b * 256 + threadIdx.x;       // < NPAD * 64
        int n = i >> 6, k = (i & 63) * 2;
        float2 v = make_float2(0.f, 0.f);
        if (n < N_NODES) v = *(const float2*)(X + (size_t)n * 128 + k);
        if (RELU) { v.x = fmaxf(v.x, 0.f); v.y = fmaxf(v.y, 0.f); }
        __nv_bfloat16 h0 = __float2bfloat16(v.x), h1 = __float2bfloat16(v.y);
        __nv_bfloat16 l0 = __float2bfloat16(v.x - __bfloat162float(h0));
        __nv_bfloat16 l1 = __float2bfloat16(v.y - __bfloat162float(h1));
        size_t o = (size_t)n * 256 + k;
        __nv_bfloat162 hh; hh.x = h0; hh.y = h1;
        __nv_bfloat162 ll; ll.x = l0; ll.y = l1;
        *(__nv_bfloat162*)&img[o] = hh;
        *(__nv_bfloat162*)&img[o + 128] = ll;
    } else {
        int i = (b - XBLKS) * 256 + threadIdx.x;
        if (i < zn4) zbuf[i] = make_float4(0.f, 0.f, 0.f, 0.f);
    }
}

// ---------------------------------------------------------------------------
// Fused transform+scatter, rel-outer / tile-inner (R13-proven):
//   block = (chunk, rel). Stage W[rel] panels ONCE (padded-136 layout),
//   then stream node tiles: stage A (float4 copy from split image), MMA,
//   epilogue into fp32 tile overlaying the A panels, scatter the (tile, rel)
//   edge bin with red.global.add.v4.
// ---------------------------------------------------------------------------
template<int OUTD>
__global__ __launch_bounds__(256)
void fused_transform_kernel(const __nv_bfloat16* __restrict__ Ximg,
                            const __nv_bfloat16* __restrict__ Wimg,
                            float* __restrict__ accOut,
                            const float4* __restrict__ pack,
                            const int* __restrict__ binCur)
{
    constexpr int LDA = 136;                 // padded bf16 stride
    constexpr int LDB = 136;
    constexpr int A_PANEL = TM * LDA;        // elems
    constexpr int B_PANEL = OUTD * LDB;
    constexpr int LDT = OUTD + 4;            // fp32 tile stride

    extern __shared__ __nv_bfloat16 sm[];
    __nv_bfloat16* sAhi = sm;
    __nv_bfloat16* sAlo = sm + A_PANEL;
    __nv_bfloat16* sBhi = sm + 2 * A_PANEL;
    __nv_bfloat16* sBlo = sBhi + B_PANEL;
    float* sTile = (float*)sm;               // overlays A panels after MMA

    constexpr int WARPS_N = 4;
    constexpr int WM = 32;                   // TM / 2
    constexpr int WN = OUTD / 4;             // 32 or 16
    constexpr int MFR = 2;                   // WM / 16
    constexpr int NFR = WN / 8;              // 4 or 2
    constexpr int NLD = (NFR + 1) / 2;

    const int tid = threadIdx.x, wid = tid >> 5, lane = tid & 31;
    const int wm0 = (wid / WARPS_N) * WM;
    const int wn0 = (wid % WARPS_N) * WN;
    const int rel = blockIdx.y;
    const int lr = lane & 15, lh = lane >> 4;

    const uint32_t aHiBase = (uint32_t)__cvta_generic_to_shared(sAhi);
    const uint32_t aLoBase = (uint32_t)__cvta_generic_to_shared(sAlo);
    const uint32_t bHiBase = (uint32_t)__cvta_generic_to_shared(sBhi);
    const uint32_t bLoBase = (uint32_t)__cvta_generic_to_shared(sBlo);

    // ---- Stage B panels ONCE: image rows (256 bf16 = 32 float4: hi|lo)
    {
        const __nv_bfloat16* gW = Wimg + (size_t)rel * OUTD * 256;
        for (int i = tid; i < OUTD * 32; i += 256) {
            int row = i >> 5, c = i & 31;
            float4 v = *(const float4*)(gW + row * 256 + c * 8);
            if (c < 16) *(float4*)&sBhi[row * LDB + c * 8] = v;
            else        *(float4*)&sBlo[row * LDB + (c - 16) * 8] = v;
        }
    }

    for (int t = blockIdx.x; t < N_TILES; t += gridDim.x) {
        __syncthreads();   // prior scatter done -> A/tile region free
        // ---- Stage A panels for tile t (float4 copy from split image)
        {
            const __nv_bfloat16* gA = Ximg + (size_t)t * TM * 256;
            for (int i = tid; i < TM * 32; i += 256) {
                int row = i >> 5, c = i & 31;
                float4 v = *(const float4*)(gA + row * 256 + c * 8);
                if (c < 16) *(float4*)&sAhi[row * LDA + c * 8] = v;
                else        *(float4*)&sAlo[row * LDA + (c - 16) * 8] = v;
            }
        }
        __syncthreads();   // A (and B on first iter) visible

        // ---- MMA: tile = A @ W^T, split bf16, 3 products into one acc
        float acc[MFR][NFR][4];
        #pragma unroll
        for (int mi = 0; mi < MFR; mi++)
            #pragma unroll
            for (int ni = 0; ni < NFR; ni++)
                #pragma unroll
                for (int q = 0; q < 4; q++) acc[mi][ni][q] = 0.f;

        #pragma unroll
        for (int k = 0; k < 8; k++) {
            const uint32_t kofs = (uint32_t)((k * 16 + lh * 8) << 1);
            uint32_t ah[MFR][4], al[MFR][4], bh[NLD][4], bl[NLD][4];
            #pragma unroll
            for (int mi = 0; mi < MFR; mi++) {
                uint32_t rofs = (uint32_t)(((wm0 + mi * 16 + lr) * LDA) << 1) + kofs;
                ldsm_x4(ah[mi], aHiBase + rofs);
                ldsm_x4(al[mi], aLoBase + rofs);
            }
            #pragma unroll
            for (int nj = 0; nj < NLD; nj++) {
                uint32_t rofs = (uint32_t)(((wn0 + nj * 16 + lr) * LDB) << 1) + kofs;
                ldsm_x4(bh[nj], bHiBase + rofs);
                ldsm_x4(bl[nj], bLoBase + rofs);
            }
            #pragma unroll
            for (int mi = 0; mi < MFR; mi++)
                #pragma unroll
                for (int ni = 0; ni < NFR; ni++) {
                    mma_bf16(acc[mi][ni], ah[mi], bh[ni >> 1][ni & 1], bh[ni >> 1][2 + (ni & 1)]);
                    mma_bf16(acc[mi][ni], ah[mi], bl[ni >> 1][ni & 1], bl[ni >> 1][2 + (ni & 1)]);
                    mma_bf16(acc[mi][ni], al[mi], bh[ni >> 1][ni & 1], bh[ni >> 1][2 + (ni & 1)]);
                }
        }
        __syncthreads();   // all warps done reading A -> overlay tile

        // ---- Epilogue: acc -> fp32 smem tile (overlaying A panels)
        #pragma unroll
        for (int mi = 0; mi < MFR; mi++)
            #pragma unroll
            for (int ni = 0; ni < NFR; ni++) {
                int row = wm0 + mi * 16 + (lane >> 2);
                int col = wn0 + ni * 8 + (lane & 3) * 2;
                *(float2*)&sTile[row * LDT + col] =
                    make_float2(acc[mi][ni][0], acc[mi][ni][1]);
                *(float2*)&sTile[(row + 8) * LDT + col] =
                    make_float2(acc[mi][ni][2], acc[mi][ni][3]);
            }
        __syncthreads();   // tile visible

        // ---- Scatter bin (t, rel): accOut[dst] += tile[row] * norm
        {
            const int bin = t * NUM_RELS + rel;
            const size_t off = (size_t)bin * BIN_CAP;
            int cnt = binCur[bin];
            if (cnt > BIN_CAP) cnt = BIN_CAP;
            if (OUTD == 128) {               // 1 edge per warp
                for (int j = wid; j < cnt; j += 8) {
                    float4 pk = pack[off + j];
                    int row = __float_as_int(pk.x);
                    int d   = __float_as_int(pk.y);
                    float nv = pk.z;
                    float4 v = *(const float4*)&sTile[row * LDT + lane * 4];
                    v.x *= nv; v.y *= nv; v.z *= nv; v.w *= nv;
                    float* p = accOut + (size_t)d * OUTD + lane * 4;
                    asm volatile("red.global.add.v4.f32 [%0], {%1, %2, %3, %4};"
                                 :: "l"(p), "f"(v.x), "f"(v.y), "f"(v.z), "f"(v.w)
                                 : "memory");
                }
            } else {                         // OUTD==64: 2 edges per warp
                const int sub = lane >> 4, l = lane & 15;
                for (int j = wid * 2; j < cnt; j += 16) {
                    int jj = j + sub;
                    if (jj < cnt) {
                        float4 pk = pack[off + jj];
                        int row = __float_as_int(pk.x);
                        int d   = __float_as_int(pk.y);
                        float nv = pk.z;
                        float4 v = *(const float4*)&sTile[row * LDT + l * 4];
                        v.x *= nv; v.y *= nv; v.z *= nv; v.w *= nv;
                        float* p = accOut + (size_t)d * OUTD + l * 4;
                        asm volatile("red.global.add.v4.f32 [%0], {%1, %2, %3, %4};"
                                     :: "l"(p), "f"(v.x), "f"(v.y), "f"(v.z), "f"(v.w)
                                     : "memory");
                    }
                }
            }
        }
    }
}

extern "C" void kernel_launch(void* const* d_in, const int* in_sizes, int n_in,
                              void* d_out, int out_size)
{
    const float* feat = (const float*)d_in[0];
    const float* norm = (const float*)d_in[1];
    const float* W1   = (const float*)d_in[2];
    const float* W2   = (const float*)d_in[3];
    const int*   src  = (const int*)d_in[4];
    const int*   dst  = (const int*)d_in[5];
    const int*   et   = (const int*)d_in[6];
    float*       out  = (float*)d_out;

    float *H;
    int *binCur;
    float4 *pack;
    __nv_bfloat16 *Ximg, *W1img, *W2img;
    cudaGetSymbolAddress((void**)&H,      g_H);
    cudaGetSymbolAddress((void**)&binCur, g_binCur);
    cudaGetSymbolAddress((void**)&pack,   g_pack);
    cudaGetSymbolAddress((void**)&Ximg,   g_X);
    cudaGetSymbolAddress((void**)&W1img,  g_W1);
    cudaGetSymbolAddress((void**)&W2img,  g_W2);

    // smem: A panels (hi+lo, also fp32 tile overlay) + B panels (hi+lo)
    constexpr int SMEM1 = (2 * TM * 136 + 2 * 128 * 136) * 2;  // 104448
    constexpr int SMEM2 = (2 * TM * 136 + 2 * 64 * 136) * 2;   //  69632
    cudaFuncSetAttribute(fused_transform_kernel<H_DIM>,
                         cudaFuncAttributeMaxDynamicSharedMemorySize, SMEM1);
    cudaFuncSetAttribute(fused_transform_kernel<OUT_DIM>,
                         cudaFuncAttributeMaxDynamicSharedMemorySize, SMEM2);

    // 1: weight prep + bin cursor reset
    combo_prep_kernel<<<dim3(NUM_RELS, 2), 256>>>(W1, W2, W1img, W2img, binCur);
    // 2: single-pass edge binning (shared by both layers)
    bin_fill_kernel<<<(N_EDGES + 255) / 256, 256>>>(src, dst, et, norm,
                                                    binCur, pack);
    // 3: split feat -> image, zero H
    prep_x_kernel<0><<<XBLKS + HBLKS, 256>>>(feat, Ximg, (float4*)H, HZ4);
    // 4: layer 1 fused  <-- ncu capture lands on my 4th launch
    fused_transform_kernel<H_DIM><<<dim3(19, NUM_RELS), 256, SMEM1>>>(
        Ximg, W1img, H, pack, binCur);
    // 5: split relu(H) -> image
    prep_x_kernel<1><<<XBLKS, 256>>>(H, Ximg, nullptr, 0);
    // 6: zero output (harness poisons to 0xAA)
    cudaMemsetAsync(out, 0, (size_t)out_size * sizeof(float));
    // 7: layer 2 fused
    fused_transform_kernel<OUT_DIM><<<dim3(28, NUM_RELS), 256, SMEM2>>>(
        Ximg, W2img, out, pack, binCur);
}

// round 15
// speedup vs baseline: 3.7037x; 1.0113x over previous
#include <cuda_runtime.h>
#include <cuda_bf16.h>
#include <cstdint>

#define N_NODES 50000
#define N_EDGES 800000
#define NUM_RELS 16
#define IN_DIM 128
#define H_DIM 128
#define OUT_DIM 64

#define TM 64                        // node tile
#define N_TILES 782                  // ceil(50000/64)
#define NPAD (N_TILES * 64)          // 50048
#define NBINS (N_TILES * NUM_RELS)   // 12512
#define BIN_CAP 160                  // fixed bin capacity (Poisson(64) tail ~1e-25)
#define XBLKS ((NPAD * 64) / 256)    // 12512 prep blocks
#define HZ4 ((N_NODES * H_DIM) / 4)  // float4 count of H
#define HBLKS ((HZ4 + 255) / 256)    // 6250

// ---------------------------------------------------------------------------
// Scratch (device globals: allocation-free rule)
// ---------------------------------------------------------------------------
__device__ float g_H[(size_t)N_NODES * H_DIM];      // 25.6 MB
__device__ int    g_binCur[NBINS];
__device__ float4 g_pack[(size_t)NBINS * BIN_CAP];  // 32 MB, slot = bin*CAP+pos
// Pre-split images, plain layout: row = 256 bf16 = [0:128) hi | [128:256) lo
__device__ __nv_bfloat16 g_X [(size_t)NPAD * 256];  // X or H split, 25.6 MB
__device__ __nv_bfloat16 g_W1[NUM_RELS * 128 * 256];// W1^T split (n-major), 1 MB
__device__ __nv_bfloat16 g_W2[NUM_RELS * 64 * 256]; // W2^T split, 0.5 MB

// ---------------------------------------------------------------------------
// Warp-MMA helpers (baseline PTX: legal on plain sm_103 target)
// ---------------------------------------------------------------------------
__device__ __forceinline__ void ldsm_x4(uint32_t r[4], uint32_t addr) {
    asm volatile("ldmatrix.sync.aligned.m8n8.x4.shared.b16 {%0,%1,%2,%3}, [%4];"
                 : "=r"(r[0]), "=r"(r[1]), "=r"(r[2]), "=r"(r[3]) : "r"(addr));
}
__device__ __forceinline__ void mma_bf16(float c[4], const uint32_t a[4],
                                         uint32_t b0, uint32_t b1) {
    asm volatile("mma.sync.aligned.m16n8k16.row.col.f32.bf16.bf16.f32 "
                 "{%0,%1,%2,%3}, {%4,%5,%6,%7}, {%8,%9}, {%0,%1,%2,%3};"
                 : "+f"(c[0]), "+f"(c[1]), "+f"(c[2]), "+f"(c[3])
                 : "r"(a[0]), "r"(a[1]), "r"(a[2]), "r"(a[3]), "r"(b0), "r"(b1));
}

// ---------------------------------------------------------------------------
// combo prep: W1+W2 -> split W^T images (n-major rows of 256: hi|lo);
// also zeroes bin cursors. grid (NUM_RELS, 2): y==0 -> W1 (+reset), y==1 -> W2.
// ---------------------------------------------------------------------------
__global__ __launch_bounds__(256)
void combo_prep_kernel(const float* __restrict__ W1, const float* __restrict__ W2,
                       __nv_bfloat16* __restrict__ w1img,
                       __nv_bfloat16* __restrict__ w2img,
                       int* __restrict__ cur)
{
    const int r = blockIdx.x, tid = threadIdx.x;
    const int OUTD = blockIdx.y == 0 ? 128 : 64;
    const float* Wr = (blockIdx.y == 0 ? W1 : W2) + (size_t)r * 128 * OUTD;
    __nv_bfloat16* img = (blockIdx.y == 0 ? w1img : w2img) + (size_t)r * OUTD * 256;
    for (int i = tid; i < OUTD * 128; i += 256) {
        int n = i >> 7, k = i & 127;
        float x = Wr[(size_t)k * OUTD + n];
        __nv_bfloat16 h = __float2bfloat16(x);
        __nv_bfloat16 l = __float2bfloat16(x - __bfloat162float(h));
        img[n * 256 + k] = h;
        img[n * 256 + 128 + k] = l;
    }
    if (blockIdx.y == 0) {
        for (int i = r * 256 + tid; i < NBINS; i += NUM_RELS * 256)
            cur[i] = 0;
    }
}

// ---------------------------------------------------------------------------
// Single-pass edge binning: key = (src>>6)*16 + etype, slot = bin*CAP + pos.
// ---------------------------------------------------------------------------
__global__ void bin_fill_kernel(const int* __restrict__ src,
                                const int* __restrict__ dstv,
                                const int* __restrict__ et,
                                const float* __restrict__ norm,
                                int* __restrict__ cur,
                                float4* __restrict__ pack)
{
    int e = blockIdx.x * 256 + threadIdx.x;
    if (e >= N_EDGES) return;
    int s = src[e];
    int bin = (s >> 6) * NUM_RELS + et[e];
    int pos = atomicAdd(&cur[bin], 1);
    if (pos < BIN_CAP) {
        float4 p;
        p.x = __int_as_float(s & 63);
        p.y = __int_as_float(dstv[e]);
        p.z = norm[e];
        p.w = 0.f;
        pack[(size_t)bin * BIN_CAP + pos] = p;
    }
}

// ---------------------------------------------------------------------------
// prep_x: fp32 [N,128] -> split hi/lo image (optional fused ReLU); extra
// grid blocks zero an accumulator buffer.
// ---------------------------------------------------------------------------
template<int RELU>
__global__ __launch_bounds__(256)
void prep_x_kernel(const float* __restrict__ X, __nv_bfloat16* __restrict__ img,
                   float4* __restrict__ zbuf, int zn4)
{
    const int b = blockIdx.x;
    if (b < XBLKS) {
        int i = b * 256 + threadIdx.x;       // < NPAD * 64
        int n = i >> 6, k = (i & 63) * 2;
        float2 v = make_float2(0.f, 0.f);
        if (n < N_NODES) v = *(const float2*)(X + (size_t)n * 128 + k);
        if (RELU) { v.x = fmaxf(v.x, 0.f); v.y = fmaxf(v.y, 0.f); }
        __nv_bfloat16 h0 = __float2bfloat16(v.x), h1 = __float2bfloat16(v.y);
        __nv_bfloat16 l0 = __float2bfloat16(v.x - __bfloat162float(h0));
        __nv_bfloat16 l1 = __float2bfloat16(v.y - __bfloat162float(h1));
        size_t o = (size_t)n * 256 + k;
        __nv_bfloat162 hh; hh.x = h0; hh.y = h1;
        __nv_bfloat162 ll; ll.x = l0; ll.y = l1;
        *(__nv_bfloat162*)&img[o] = hh;
        *(__nv_bfloat162*)&img[o + 128] = ll;
    } else {
        int i = (b - XBLKS) * 256 + threadIdx.x;
        if (i < zn4) zbuf[i] = make_float4(0.f, 0.f, 0.f, 0.f);
    }
}

// ---------------------------------------------------------------------------
// Fused transform+scatter, rel-outer / tile-inner (R14 base) with manually
// software-pipelined fragment loads: double-buffered register fragment sets
// so the ldmatrix for k+1 issues before the dependent MMAs of k, covering
// the ~29cyc LDS latency with tensor work.
// ---------------------------------------------------------------------------
template<int OUTD>
__global__ __launch_bounds__(256, (OUTD == 64) ? 3 : 2)
void fused_transform_kernel(const __nv_bfloat16* __restrict__ Ximg,
                            const __nv_bfloat16* __restrict__ Wimg,
                            float* __restrict__ accOut,
                            const float4* __restrict__ pack,
                            const int* __restrict__ binCur)
{
    constexpr int LDA = 136;                 // padded bf16 stride
    constexpr int LDB = 136;
    constexpr int A_PANEL = TM * LDA;        // elems
    constexpr int B_PANEL = OUTD * LDB;
    constexpr int LDT = OUTD + 4;            // fp32 tile stride

    extern __shared__ __nv_bfloat16 sm[];
    __nv_bfloat16* sAhi = sm;
    __nv_bfloat16* sAlo = sm + A_PANEL;
    __nv_bfloat16* sBhi = sm + 2 * A_PANEL;
    __nv_bfloat16* sBlo = sBhi + B_PANEL;
    float* sTile = (float*)sm;               // overlays A panels after MMA

    constexpr int WARPS_N = 4;
    constexpr int WM = 32;                   // TM / 2
    constexpr int WN = OUTD / 4;             // 32 or 16
    constexpr int MFR = 2;                   // WM / 16
    constexpr int NFR = WN / 8;              // 4 or 2
    constexpr int NLD = (NFR + 1) / 2;

    const int tid = threadIdx.x, wid = tid >> 5, lane = tid & 31;
    const int wm0 = (wid / WARPS_N) * WM;
    const int wn0 = (wid % WARPS_N) * WN;
    const int rel = blockIdx.y;
    const int lr = lane & 15, lh = lane >> 4;

    const uint32_t aHiBase = (uint32_t)__cvta_generic_to_shared(sAhi);
    const uint32_t aLoBase = (uint32_t)__cvta_generic_to_shared(sAlo);
    const uint32_t bHiBase = (uint32_t)__cvta_generic_to_shared(sBhi);
    const uint32_t bLoBase = (uint32_t)__cvta_generic_to_shared(sBlo);

    // Per-lane base offsets (k-invariant parts)
    const uint32_t aRow0 = (uint32_t)(((wm0 + lr) * LDA) << 1);
    const uint32_t aRow1 = (uint32_t)(((wm0 + 16 + lr) * LDA) << 1);
    const uint32_t bRow0 = (uint32_t)(((wn0 + lr) * LDB) << 1);
    const uint32_t bRow1 = (uint32_t)(((wn0 + 16 + lr) * LDB) << 1);

    // ---- Stage B panels ONCE: image rows (256 bf16 = 32 float4: hi|lo)
    {
        const __nv_bfloat16* gW = Wimg + (size_t)rel * OUTD * 256;
        for (int i = tid; i < OUTD * 32; i += 256) {
            int row = i >> 5, c = i & 31;
            float4 v = *(const float4*)(gW + row * 256 + c * 8);
            if (c < 16) *(float4*)&sBhi[row * LDB + c * 8] = v;
            else        *(float4*)&sBlo[row * LDB + (c - 16) * 8] = v;
        }
    }

    for (int t = blockIdx.x; t < N_TILES; t += gridDim.x) {
        __syncthreads();   // prior scatter done -> A/tile region free
        // ---- Stage A panels for tile t (float4 copy from split image)
        {
            const __nv_bfloat16* gA = Ximg + (size_t)t * TM * 256;
            for (int i = tid; i < TM * 32; i += 256) {
                int row = i >> 5, c = i & 31;
                float4 v = *(const float4*)(gA + row * 256 + c * 8);
                if (c < 16) *(float4*)&sAhi[row * LDA + c * 8] = v;
                else        *(float4*)&sAlo[row * LDA + (c - 16) * 8] = v;
            }
        }
        __syncthreads();   // A (and B on first iter) visible

        // ---- MMA with double-buffered register fragments
        float acc[MFR][NFR][4];
        #pragma unroll
        for (int mi = 0; mi < MFR; mi++)
            #pragma unroll
            for (int ni = 0; ni < NFR; ni++)
                #pragma unroll
                for (int q = 0; q < 4; q++) acc[mi][ni][q] = 0.f;

        uint32_t ah[2][MFR][4], al[2][MFR][4], bh[2][NLD][4], bl[2][NLD][4];

        // fragment fetch for k-step kk into set s
        #define FETCH_FRAGS(s, kk) do {                                        \
            const uint32_t _ko = (uint32_t)(((kk) * 16 + lh * 8) << 1);        \
            ldsm_x4(ah[s][0], aHiBase + aRow0 + _ko);                          \
            ldsm_x4(al[s][0], aLoBase + aRow0 + _ko);                          \
            ldsm_x4(ah[s][1], aHiBase + aRow1 + _ko);                          \
            ldsm_x4(al[s][1], aLoBase + aRow1 + _ko);                          \
            ldsm_x4(bh[s][0], bHiBase + bRow0 + _ko);                          \
            ldsm_x4(bl[s][0], bLoBase + bRow0 + _ko);                          \
            if (NLD > 1) {                                                     \
                ldsm_x4(bh[s][NLD - 1], bHiBase + bRow1 + _ko);                \
                ldsm_x4(bl[s][NLD - 1], bLoBase + bRow1 + _ko);                \
            }                                                                  \
        } while (0)

        FETCH_FRAGS(0, 0);
        #pragma unroll
        for (int k = 0; k < 8; k++) {
            const int cur = k & 1, nxt = cur ^ 1;
            if (k < 7) FETCH_FRAGS(nxt, k + 1);   // prefetch before dependent MMAs
            #pragma unroll
            for (int mi = 0; mi < MFR; mi++)
                #pragma unroll
                for (int ni = 0; ni < NFR; ni++) {
                    uint32_t b0h = bh[cur][ni >> 1][ni & 1];
                    uint32_t b1h = bh[cur][ni >> 1][2 + (ni & 1)];
                    uint32_t b0l = bl[cur][ni >> 1][ni & 1];
                    uint32_t b1l = bl[cur][ni >> 1][2 + (ni & 1)];
                    mma_bf16(acc[mi][ni], ah[cur][mi], b0h, b1h);
                    mma_bf16(acc[mi][ni], ah[cur][mi], b0l, b1l);
                    mma_bf16(acc[mi][ni], al[cur][mi], b0h, b1h);
                }
        }
        #undef FETCH_FRAGS
        __syncthreads();   // all warps done reading A -> overlay tile

        // ---- Epilogue: acc -> fp32 smem tile (overlaying A panels)
        #pragma unroll
        for (int mi = 0; mi < MFR; mi++)
            #pragma unroll
            for (int ni = 0; ni < NFR; ni++) {
                int row = wm0 + mi * 16 + (lane >> 2);
                int col = wn0 + ni * 8 + (lane & 3) * 2;
                *(float2*)&sTile[row * LDT + col] =
                    make_float2(acc[mi][ni][0], acc[mi][ni][1]);
                *(float2*)&sTile[(row + 8) * LDT + col] =
                    make_float2(acc[mi][ni][2], acc[mi][ni][3]);
            }
        __syncthreads();   // tile visible

        // ---- Scatter bin (t, rel): accOut[dst] += tile[row] * norm
        {
            const int bin = t * NUM_RELS + rel;
            const size_t off = (size_t)bin * BIN_CAP;
            int cnt = binCur[bin];
            if (cnt > BIN_CAP) cnt = BIN_CAP;
            if (OUTD == 128) {               // 1 edge per warp
                for (int j = wid; j < cnt; j += 8) {
                    float4 pk = pack[off + j];
                    int row = __float_as_int(pk.x);
                    int d   = __float_as_int(pk.y);
                    float nv = pk.z;
                    float4 v = *(const float4*)&sTile[row * LDT + lane * 4];
                    v.x *= nv; v.y *= nv; v.z *= nv; v.w *= nv;
                    float* p = accOut + (size_t)d * OUTD + lane * 4;
                    asm volatile("red.global.add.v4.f32 [%0], {%1, %2, %3, %4};"
                                 :: "l"(p), "f"(v.x), "f"(v.y), "f"(v.z), "f"(v.w)
                                 : "memory");
                }
            } else {                         // OUTD==64: 2 edges per warp
                const int sub = lane >> 4, l = lane & 15;
                for (int j = wid * 2; j < cnt; j += 16) {
                    int jj = j + sub;
                    if (jj < cnt) {
                        float4 pk = pack[off + jj];
                        int row = __float_as_int(pk.x);
                        int d   = __float_as_int(pk.y);
                        float nv = pk.z;
                        float4 v = *(const float4*)&sTile[row * LDT + l * 4];
                        v.x *= nv; v.y *= nv; v.z *= nv; v.w *= nv;
                        float* p = accOut + (size_t)d * OUTD + l * 4;
                        asm volatile("red.global.add.v4.f32 [%0], {%1, %2, %3, %4};"
                                     :: "l"(p), "f"(v.x), "f"(v.y), "f"(v.z), "f"(v.w)
                                     : "memory");
                    }
                }
            }
        }
    }
}

extern "C" void kernel_launch(void* const* d_in, const int* in_sizes, int n_in,
                              void* d_out, int out_size)
{
    const float* feat = (const float*)d_in[0];
    const float* norm = (const float*)d_in[1];
    const float* W1   = (const float*)d_in[2];
    const float* W2   = (const float*)d_in[3];
    const int*   src  = (const int*)d_in[4];
    const int*   dst  = (const int*)d_in[5];
    const int*   et   = (const int*)d_in[6];
    float*       out  = (float*)d_out;

    float *H;
    int *binCur;
    float4 *pack;
    __nv_bfloat16 *Ximg, *W1img, *W2img;
    cudaGetSymbolAddress((void**)&H,      g_H);
    cudaGetSymbolAddress((void**)&binCur, g_binCur);
    cudaGetSymbolAddress((void**)&pack,   g_pack);
    cudaGetSymbolAddress((void**)&Ximg,   g_X);
    cudaGetSymbolAddress((void**)&W1img,  g_W1);
    cudaGetSymbolAddress((void**)&W2img,  g_W2);

    // smem: A panels (hi+lo, also fp32 tile overlay) + B panels (hi+lo)
    constexpr int SMEM1 = (2 * TM * 136 + 2 * 128 * 136) * 2;  // 104448
    constexpr int SMEM2 = (2 * TM * 136 + 2 * 64 * 136) * 2;   //  69632
    cudaFuncSetAttribute(fused_transform_kernel<H_DIM>,
                         cudaFuncAttributeMaxDynamicSharedMemorySize, SMEM1);
    cudaFuncSetAttribute(fused_transform_kernel<OUT_DIM>,
                         cudaFuncAttributeMaxDynamicSharedMemorySize, SMEM2);

    // 1: weight prep + bin cursor reset
    combo_prep_kernel<<<dim3(NUM_RELS, 2), 256>>>(W1, W2, W1img, W2img, binCur);
    // 2: single-pass edge binning (shared by both layers)
    bin_fill_kernel<<<(N_EDGES + 255) / 256, 256>>>(src, dst, et, norm,
                                                    binCur, pack);
    // 3: split feat -> image, zero H
    prep_x_kernel<0><<<XBLKS + HBLKS, 256>>>(feat, Ximg, (float4*)H, HZ4);
    // 4: layer 1 fused  <-- ncu capture lands on my 4th launch
    fused_transform_kernel<H_DIM><<<dim3(19, NUM_RELS), 256, SMEM1>>>(
        Ximg, W1img, H, pack, binCur);
    // 5: split relu(H) -> image
    prep_x_kernel<1><<<XBLKS, 256>>>(H, Ximg, nullptr, 0);
    // 6: zero output (harness poisons to 0xAA)
    cudaMemsetAsync(out, 0, (size_t)out_size * sizeof(float));
    // 7: layer 2 fused
    fused_transform_kernel<OUT_DIM><<<dim3(28, NUM_RELS), 256, SMEM2>>>(
        Ximg, W2img, out, pack, binCur);
}